// round 13
// baseline (speedup 1.0000x reference)
#include <cuda_runtime.h>

#define P_N 200000
#define C_N 50000
#define L_N 8
#define F_N 32
#define DIN 64
#define NSTEPS 5

#define PB_BLOCKS ((P_N + 255) / 256)   // histogram blocks
#define BI_TILE 128
#define PB2 ((P_N + BI_TILE - 1) / BI_TILE)   // 1563
#define CB2 ((C_N + BI_TILE - 1) / BI_TILE)   // 391

#define STILE 128                       // scan paths per block
#define SROW 260                        // floats per h-pair row
#define L2TILE 64
#define PS2 68                          // float stride for layer2 staging
#define XS 132                          // float stride for buildinit staging

typedef unsigned long long u64;

// ---------------- device scratch ----------------
__device__ float g_p[(size_t)P_N * F_N];
__device__ int   g_order[P_N];
__device__ int   g_idx[(size_t)P_N * L_N];
__device__ int   g_len[P_N];
__device__ float g_agg[(size_t)C_N * F_N];
__device__ float g_table[(size_t)C_N * 96];
__device__ int   g_cnt[16];
__device__ int   g_blkhist[PB_BLOCKS * 8];
__device__ int   g_done;

// ---------------- helpers ----------------
__device__ __forceinline__ u64 ffma2(u64 a, u64 b, u64 c) {
    u64 d;
    asm("fma.rn.f32x2 %0, %1, %2, %3;" : "=l"(d) : "l"(a), "l"(b), "l"(c));
    return d;
}
__device__ __forceinline__ float2 u2f(u64 v) {
    float2 r;
    asm("mov.b64 {%0,%1}, %2;" : "=f"(r.x), "=f"(r.y) : "l"(v));
    return r;
}
__device__ __forceinline__ u64 f2u(float a, float b) {
    u64 r;
    asm("mov.b64 %0, {%1,%2};" : "=l"(r) : "f"(a), "f"(b));
    return r;
}

__device__ __forceinline__ float tanh_ap(float x) {
    float y;
    asm("tanh.approx.f32 %0, %1;" : "=f"(y) : "f"(x));
    return y;
}
__device__ __forceinline__ float fast_sigmoid(float v) {
    return fmaf(0.5f, tanh_ap(0.5f * v), 0.5f);
}
__device__ __forceinline__ float fast_tanh(float v) { return tanh_ap(v); }

__device__ __forceinline__ void red_add_v4(float* p, float4 v) {
    asm volatile("red.global.add.v4.f32 [%0], {%1,%2,%3,%4};"
                 :: "l"(p), "f"(v.x), "f"(v.y), "f"(v.z), "f"(v.w) : "memory");
}
__device__ __forceinline__ u64 ldg64(const u64* p) {
    u64 v;
    asm("ld.global.nc.b64 %0, [%1];" : "=l"(v) : "l"(p));
    return v;
}

// ---------------- fused hist + prefix (last-block-done) ----------------
__global__ void __launch_bounds__(256) hist_prefix_kernel(const int* __restrict__ plen) {
    __shared__ int lh[8];
    __shared__ int slast;
    int tid = threadIdx.x;
    if (tid < 8) lh[tid] = 0;
    __syncthreads();
    int i = blockIdx.x * 256 + tid;
    if (i < P_N) {
        int b = plen[i]; b = b < 0 ? 0 : (b > 7 ? 7 : b);
        atomicAdd(&lh[b], 1);
    }
    __syncthreads();
    if (tid < 8) g_blkhist[blockIdx.x * 8 + tid] = lh[tid];
    __threadfence();
    if (tid == 0) {
        int t = atomicAdd(&g_done, 1);
        slast = (t == gridDim.x - 1) ? 1 : 0;
    }
    __syncthreads();
    if (slast) {
        __threadfence();
        int local[8] = {0, 0, 0, 0, 0, 0, 0, 0};
        for (int j = tid; j < PB_BLOCKS; j += 256) {
#pragma unroll
            for (int b = 0; b < 8; b++) local[b] += g_blkhist[j * 8 + b];
        }
        if (tid < 8) lh[tid] = 0;
        __syncthreads();
#pragma unroll
        for (int b = 0; b < 8; b++) atomicAdd(&lh[b], local[b]);
        __syncthreads();
        if (tid == 0) {
            int acc = 0;
#pragma unroll
            for (int b = 7; b >= 0; b--) { int cv = lh[b]; g_cnt[b] = acc; acc += cv; }
            g_done = 0;
        }
    }
}

__global__ void __launch_bounds__(256) scatter_kernel(const int* __restrict__ plen) {
    int i = blockIdx.x * 256 + threadIdx.x;
    if (i < P_N) {
        int b = plen[i]; b = b < 0 ? 0 : (b > 7 ? 7 : b);
        int pos = atomicAdd(&g_cnt[b], 1);
        g_order[pos] = i;
    }
}

// ---------------- tiled buildinit: paths (init p) + channels (init c + gi1 table) ----------------
__global__ void __launch_bounds__(256, 2) buildinit_gi_kernel(const int* __restrict__ plen,
                                                              const int* __restrict__ pci,
                                                              const float* __restrict__ praw,
                                                              const float* __restrict__ craw,
                                                              const float* __restrict__ Wp,
                                                              const float* __restrict__ bp,
                                                              const float* __restrict__ Wc,
                                                              const float* __restrict__ bc,
                                                              const float* __restrict__ Wi1,
                                                              const float* __restrict__ bi1,
                                                              const float* __restrict__ bh1,
                                                              float* __restrict__ c)
{
    __shared__ __align__(16) float sxx[64 * XS];
    __shared__ __align__(16) u64   sww[32 * 48];
    __shared__ int   sord[BI_TILE];
    __shared__ float sb[32];
    __shared__ float sb1[96];

    int tid = threadIdx.x;
    bool isPath = blockIdx.x < PB2;
    int s0 = isPath ? blockIdx.x * BI_TILE : (blockIdx.x - PB2) * BI_TILE;
    int rcount = isPath ? min(BI_TILE, P_N - s0) : min(BI_TILE, C_N - s0);
    const float* W = isPath ? Wp : Wc;
    const float* b = isPath ? bp : bc;
    const float* xsrc = isPath ? praw : craw;

    for (int i = tid; i < 64 * 16; i += 256) {
        int d = i >> 4, o = i & 15;
        const float2* wp2 = (const float2*)(W + d * 32);
        float2 w = wp2[o];
        sww[d * 16 + o] = f2u(w.x, w.y);
    }
    if (tid < 32) sb[tid] = b[tid];
    if (!isPath && tid < 96) sb1[tid] = bi1[tid] + (tid < 64 ? bh1[tid] : 0.0f);

    if (isPath) {
        if (tid < BI_TILE) {
            int row = s0 + tid;
            if (row < P_N) {
                int sr = g_order[row];
                sord[tid] = sr;
                g_len[row] = plen[sr];
                const int4* si = (const int4*)(pci + (size_t)sr * L_N);
                int4* di = (int4*)(g_idx + (size_t)row * L_N);
                di[0] = si[0]; di[1] = si[1];
            }
        }
    }
    __syncthreads();

    for (int i = tid; i < rcount * 16; i += 256) {
        int r = i >> 4, q = i & 15;
        int sr = isPath ? sord[r] : (s0 + r);
        float4 v = ((const float4*)(xsrc + (size_t)sr * DIN))[q];
        sxx[(4 * q + 0) * XS + r] = v.x;
        sxx[(4 * q + 1) * XS + r] = v.y;
        sxx[(4 * q + 2) * XS + r] = v.z;
        sxx[(4 * q + 3) * XS + r] = v.w;
    }
    __syncthreads();

    int px = tid >> 4, fy = tid & 15;
    int pbase = px * 8;

    u64 acc[8];
#pragma unroll
    for (int p = 0; p < 8; p++) acc[p] = 0ull;
#pragma unroll 4
    for (int k = 0; k < 64; k++) {
        u64 w = sww[k * 16 + fy];
        const float4* xr = (const float4*)(sxx + k * XS + pbase);
        float4 a = xr[0], bq = xr[1];
        float xv[8] = {a.x, a.y, a.z, a.w, bq.x, bq.y, bq.z, bq.w};
#pragma unroll
        for (int p = 0; p < 8; p++)
            acc[p] = ffma2(f2u(xv[p], xv[p]), w, acc[p]);
    }

    float* dst = isPath ? g_p : c;
    float cres[8][2];
    float b0 = sb[2 * fy], b1 = sb[2 * fy + 1];
#pragma unroll
    for (int p = 0; p < 8; p++) {
        int pp = pbase + p;
        float2 v = u2f(acc[p]);
        float r0 = fmaxf(v.x + b0, 0.0f);
        float r1 = fmaxf(v.y + b1, 0.0f);
        cres[p][0] = r0; cres[p][1] = r1;
        if (pp < rcount)
            ((u64*)(dst + (size_t)(s0 + pp) * F_N))[fy] = f2u(r0, r1);
    }

    if (isPath) return;

    __syncthreads();
    for (int i = tid; i < rcount * 8; i += 256)
        ((float4*)(g_agg + (size_t)s0 * F_N))[i] = make_float4(0.f, 0.f, 0.f, 0.f);
#pragma unroll
    for (int p = 0; p < 8; p++) {
        int pp = pbase + p;
        if (pp < rcount) {
            sxx[(2 * fy) * XS + pp]     = cres[p][0];
            sxx[(2 * fy + 1) * XS + pp] = cres[p][1];
        }
    }
    for (int i = tid; i < 32 * 48; i += 256) {
        int k = i / 48, po = i % 48;
        sww[k * 48 + po] = f2u(Wi1[(2 * po) * 32 + k], Wi1[(2 * po + 1) * 32 + k]);
    }
    __syncthreads();

    u64 tr[8], tz[8], tn[8];
#pragma unroll
    for (int p = 0; p < 8; p++) { tr[p] = 0ull; tz[p] = 0ull; tn[p] = 0ull; }
#pragma unroll 4
    for (int k = 0; k < 32; k++) {
        const u64* wrow = sww + k * 48;
        u64 wr = wrow[fy], wz = wrow[16 + fy], wn = wrow[32 + fy];
        const float4* xr = (const float4*)(sxx + k * XS + pbase);
        float4 a = xr[0], bq = xr[1];
        float xv[8] = {a.x, a.y, a.z, a.w, bq.x, bq.y, bq.z, bq.w};
#pragma unroll
        for (int p = 0; p < 8; p++) {
            u64 d = f2u(xv[p], xv[p]);
            tr[p] = ffma2(d, wr, tr[p]);
            tz[p] = ffma2(d, wz, tz[p]);
            tn[p] = ffma2(d, wn, tn[p]);
        }
    }
    float br0 = sb1[2 * fy],      br1 = sb1[2 * fy + 1];
    float bz0 = sb1[32 + 2 * fy], bz1 = sb1[32 + 2 * fy + 1];
    float bn0 = sb1[64 + 2 * fy], bn1 = sb1[64 + 2 * fy + 1];
#pragma unroll
    for (int p = 0; p < 8; p++) {
        int pp = pbase + p;
        if (pp < rcount) {
            u64* trow = (u64*)(g_table + (size_t)(s0 + pp) * 96);
            float2 a0 = u2f(tr[p]), a1 = u2f(tz[p]), a2 = u2f(tn[p]);
            trow[fy]      = f2u(a0.x + br0, a0.y + br1);
            trow[16 + fy] = f2u(a1.x + bz0, a1.y + bz1);
            trow[32 + fy] = f2u(a2.x + bn0, a2.y + bn1);
        }
    }
}

// ---------------- scan10: warp-autonomous, pairwise-prefetch epilogue, no hreg ----------------
// 128 paths/block, 256 thr = 16(px) x 16(fy), tile 8 paths x 6 outs.
__global__ void __launch_bounds__(256, 2) scan10_kernel(const float* __restrict__ Wh,
                                                        const float* __restrict__ bh,
                                                        float* __restrict__ final_out)
{
    __shared__ __align__(16) u64   sww[32 * 48];     // [k][out-pair]
    __shared__ __align__(16) float shf[16 * SROW];   // single buffer [f-pair row][2p + (f&1)]
    __shared__ unsigned short sidx[STILE * L_N];
    __shared__ short slen[STILE];
    __shared__ float sbhn[32];

    int tid = threadIdx.x;
    int s0 = blockIdx.x * STILE;
    int pcount = min(STILE, P_N - s0);

    for (int i = tid; i < 32 * 48; i += 256) {
        int k = i / 48, po = i % 48;
        sww[k * 48 + po] = f2u(Wh[(2 * po) * 32 + k], Wh[(2 * po + 1) * 32 + k]);
    }
    if (tid < 32) sbhn[tid] = bh[64 + tid];
    if (tid < STILE) slen[tid] = (tid < pcount) ? (short)g_len[s0 + tid] : (short)-1;
    for (int i = tid; i < STILE * L_N; i += 256)
        sidx[i] = (i < pcount * L_N) ? (unsigned short)g_idx[(size_t)s0 * L_N + i] : (unsigned short)0;
    if (pcount < STILE) {
        for (int i = tid; i < 16 * SROW; i += 256) shf[i] = 0.0f;
        __syncthreads();
    }
    for (int i = tid; i < pcount * 8; i += 256) {
        int p = i >> 3, kq = i & 7;
        float4 v = ((const float4*)(g_p + (size_t)s0 * F_N))[i];
        float* r0 = &shf[(2 * kq) * SROW + 2 * p];
        r0[0] = v.x; r0[1] = v.y;
        float* r1 = &shf[(2 * kq + 1) * SROW + 2 * p];
        r1[0] = v.z; r1[1] = v.w;
    }
    __syncthreads();

    int px = tid >> 4;                  // 0..15
    int fy = tid & 15;                  // 0..15
    int pbase = px * 8;
    int wfirst = (tid >> 5) * 16;       // first path of this warp
    int tmax = slen[wfirst];            // per-WARP max (sorted descending)

    for (int t = 0; t <= tmax; t++) {
        u64 ar[8], az[8], an[8];
#pragma unroll
        for (int p = 0; p < 8; p++) { ar[p] = 0ull; az[p] = 0ull; an[p] = 0ull; }

#pragma unroll 4
        for (int j = 0; j < 16; j++) {          // k-pair: k = 2j, 2j+1
            const u64* w0 = sww + (2 * j) * 48;
            const u64* w1 = sww + (2 * j + 1) * 48;
            u64 wr0 = w0[fy], wz0 = w0[16 + fy], wn0 = w0[32 + fy];
            u64 wr1 = w1[fy], wz1 = w1[16 + fy], wn1 = w1[32 + fy];
            const float4* hq = (const float4*)(shf + j * SROW + 2 * pbase);
            float4 q0 = hq[0], q1 = hq[1], q2 = hq[2], q3 = hq[3];
            float qe[8] = {q0.x, q0.z, q1.x, q1.z, q2.x, q2.z, q3.x, q3.z};
            float qo[8] = {q0.y, q0.w, q1.y, q1.w, q2.y, q2.w, q3.y, q3.w};
#pragma unroll
            for (int p = 0; p < 8; p++) {
                u64 he = f2u(qe[p], qe[p]);
                ar[p] = ffma2(he, wr0, ar[p]);
                az[p] = ffma2(he, wz0, az[p]);
                an[p] = ffma2(he, wn0, an[p]);
                u64 ho = f2u(qo[p], qo[p]);
                ar[p] = ffma2(ho, wr1, ar[p]);
                az[p] = ffma2(ho, wz1, az[p]);
                an[p] = ffma2(ho, wn1, an[p]);
            }
        }
        __syncwarp();   // all group reads of shf done before in-place writes

        // epilogue: paths in pairs; prefetch next pair's 6 table u64 while doing
        // two paths of gate math. hold read from shf (no hreg).
        {
            u64 ga0, ga1, ga2, gb0, gb1, gb2;
            {
                int cha = sidx[(pbase + 0) * L_N + t];
                const u64* tga = (const u64*)(g_table + (size_t)cha * 96);
                ga0 = ldg64(tga + fy); ga1 = ldg64(tga + 16 + fy); ga2 = ldg64(tga + 32 + fy);
                int chb = sidx[(pbase + 1) * L_N + t];
                const u64* tgb = (const u64*)(g_table + (size_t)chb * 96);
                gb0 = ldg64(tgb + fy); gb1 = ldg64(tgb + 16 + fy); gb2 = ldg64(tgb + 32 + fy);
            }
#pragma unroll
            for (int pr = 0; pr < 4; pr++) {
                u64 na0 = 0, na1 = 0, na2 = 0, nb0 = 0, nb1 = 0, nb2 = 0;
                if (pr < 3) {
                    int cha = sidx[(pbase + 2 * pr + 2) * L_N + t];
                    const u64* tga = (const u64*)(g_table + (size_t)cha * 96);
                    na0 = ldg64(tga + fy); na1 = ldg64(tga + 16 + fy); na2 = ldg64(tga + 32 + fy);
                    int chb = sidx[(pbase + 2 * pr + 3) * L_N + t];
                    const u64* tgb = (const u64*)(g_table + (size_t)chb * 96);
                    nb0 = ldg64(tgb + fy); nb1 = ldg64(tgb + 16 + fy); nb2 = ldg64(tgb + 32 + fy);
                }
#pragma unroll
                for (int s = 0; s < 2; s++) {
                    int pp = pbase + 2 * pr + s;
                    u64 cg0 = s ? gb0 : ga0;
                    u64 cg1 = s ? gb1 : ga1;
                    u64 cg2 = s ? gb2 : ga2;
                    int p = 2 * pr + s;
                    bool active = (t <= slen[pp]);
                    float2 gr = u2f(cg0), gz = u2f(cg1), gn = u2f(cg2);
                    float2 vr = u2f(ar[p]), vz = u2f(az[p]), vn = u2f(an[p]);
                    float2 hold = *(const float2*)(shf + fy * SROW + 2 * pp);
                    float h0, h1;
                    {
                        float r = fast_sigmoid(gr.x + vr.x);
                        float z = fast_sigmoid(gz.x + vz.x);
                        float n = fast_tanh(gn.x + r * (vn.x + sbhn[2 * fy]));
                        h0 = n + z * (hold.x - n);
                    }
                    {
                        float r = fast_sigmoid(gr.y + vr.y);
                        float z = fast_sigmoid(gz.y + vz.y);
                        float n = fast_tanh(gn.y + r * (vn.y + sbhn[2 * fy + 1]));
                        h1 = n + z * (hold.y - n);
                    }
                    if (active)
                        *(float2*)(shf + fy * SROW + 2 * pp) = make_float2(h0, h1);
                }
                ga0 = na0; ga1 = na1; ga2 = na2;
                gb0 = nb0; gb1 = nb1; gb2 = nb2;
            }
        }
        __syncwarp();   // group writes visible before next k-loop
    }

    __syncthreads();   // all warps done before cross-warp tail reads

    // tail: 2 threads per path (kc = feature half) — write back + atomics
    int p = tid & (STILE - 1);
    int kc = tid >> 7;
    if (p < pcount) {
        float v[16];
#pragma unroll
        for (int j = 0; j < 16; j++) {
            int f = kc * 16 + j;
            v[j] = shf[(f >> 1) * SROW + 2 * p + (f & 1)];
        }
        float4* dst;
        if (final_out) {
            int ord = g_order[s0 + p];
            dst = (float4*)(final_out + (size_t)ord * F_N + kc * 16);
        } else {
            dst = (float4*)(g_p + (size_t)(s0 + p) * F_N + kc * 16);
        }
#pragma unroll
        for (int q = 0; q < 4; q++)
            dst[q] = make_float4(v[4 * q], v[4 * q + 1], v[4 * q + 2], v[4 * q + 3]);
        int ln = slen[p];
#pragma unroll 1
        for (int t = 0; t <= ln; t++) {
            int ch = sidx[p * L_N + t];
            float* base = g_agg + (size_t)ch * F_N + kc * 16;
            red_add_v4(base + 0,  make_float4(v[0],  v[1],  v[2],  v[3]));
            red_add_v4(base + 4,  make_float4(v[4],  v[5],  v[6],  v[7]));
            red_add_v4(base + 8,  make_float4(v[8],  v[9],  v[10], v[11]));
            red_add_v4(base + 12, make_float4(v[12], v[13], v[14], v[15]));
        }
    }
}

// ---------------- layer2f: FUSED gi2+gh2 k-loop, then epilogue, then gi1 table ----------------
__global__ void __launch_bounds__(256, 2) layer2f_kernel(float* __restrict__ c,
                                                         const float* __restrict__ Wi2,
                                                         const float* __restrict__ Wh2,
                                                         const float* __restrict__ bi2,
                                                         const float* __restrict__ bh2,
                                                         const float* __restrict__ Wi1,
                                                         const float* __restrict__ bi1,
                                                         const float* __restrict__ bh1,
                                                         int want_table)
{
    __shared__ __align__(16) u64   swa[32 * 48];
    __shared__ __align__(16) u64   swh[32 * 48];
    __shared__ __align__(16) float sagg[32 * PS2];
    __shared__ __align__(16) float sc[32 * PS2];
    __shared__ float sbi[96];
    __shared__ float sbhn2[32];
    __shared__ float sb1[96];

    int tid = threadIdx.x;
    int s0 = blockIdx.x * L2TILE;
    int rcount = min(L2TILE, C_N - s0);

    for (int i = tid; i < 32 * 48; i += 256) {
        int k = i / 48, po = i % 48;
        swa[k * 48 + po] = f2u(Wi2[(2 * po) * 32 + k], Wi2[(2 * po + 1) * 32 + k]);
        swh[k * 48 + po] = f2u(Wh2[(2 * po) * 32 + k], Wh2[(2 * po + 1) * 32 + k]);
    }
    if (tid < 96) {
        sbi[tid] = bi2[tid] + (tid < 64 ? bh2[tid] : 0.0f);
        sb1[tid] = bi1[tid] + (tid < 64 ? bh1[tid] : 0.0f);
    }
    if (tid < 32) sbhn2[tid] = bh2[64 + tid];
    if (rcount < L2TILE) {
        for (int i = tid; i < 32 * L2TILE; i += 256) {
            int p = i & (L2TILE - 1);
            if (p >= rcount) { sagg[(i >> 6) * PS2 + p] = 0.0f; sc[(i >> 6) * PS2 + p] = 0.0f; }
        }
    }
    for (int i = tid; i < rcount * 8; i += 256) {
        int p = i >> 3, kq = i & 7;
        float4 va = ((const float4*)(g_agg + (size_t)s0 * F_N))[i];
        sagg[(4 * kq + 0) * PS2 + p] = va.x;
        sagg[(4 * kq + 1) * PS2 + p] = va.y;
        sagg[(4 * kq + 2) * PS2 + p] = va.z;
        sagg[(4 * kq + 3) * PS2 + p] = va.w;
        ((float4*)(g_agg + (size_t)s0 * F_N))[i] = make_float4(0.f, 0.f, 0.f, 0.f);
        float4 vc = ((const float4*)(c + (size_t)s0 * F_N))[i];
        sc[(4 * kq + 0) * PS2 + p] = vc.x;
        sc[(4 * kq + 1) * PS2 + p] = vc.y;
        sc[(4 * kq + 2) * PS2 + p] = vc.z;
        sc[(4 * kq + 3) * PS2 + p] = vc.w;
    }
    __syncthreads();

    int px = tid >> 4, fy = tid & 15;
    int pbase = px * 4;

    u64 ir[4], iz[4], in_[4], hr_[4], hz_[4], hn_[4];
#pragma unroll
    for (int p = 0; p < 4; p++) {
        ir[p] = 0ull; iz[p] = 0ull; in_[p] = 0ull;
        hr_[p] = 0ull; hz_[p] = 0ull; hn_[p] = 0ull;
    }
#pragma unroll 4
    for (int k = 0; k < 32; k++) {
        const u64* wA = swa + k * 48;
        const u64* wH = swh + k * 48;
        u64 war = wA[fy], waz = wA[16 + fy], wan = wA[32 + fy];
        u64 whr = wH[fy], whz = wH[16 + fy], whn = wH[32 + fy];
        float4 va = *(const float4*)(sagg + k * PS2 + pbase);
        float4 vc = *(const float4*)(sc + k * PS2 + pbase);
        float av[4] = {va.x, va.y, va.z, va.w};
        float cv[4] = {vc.x, vc.y, vc.z, vc.w};
#pragma unroll
        for (int p = 0; p < 4; p++) {
            u64 da = f2u(av[p], av[p]);
            ir[p]  = ffma2(da, war, ir[p]);
            iz[p]  = ffma2(da, waz, iz[p]);
            in_[p] = ffma2(da, wan, in_[p]);
            u64 dc = f2u(cv[p], cv[p]);
            hr_[p] = ffma2(dc, whr, hr_[p]);
            hz_[p] = ffma2(dc, whz, hz_[p]);
            hn_[p] = ffma2(dc, whn, hn_[p]);
        }
    }

    float hn2[4][2];
#pragma unroll
    for (int p = 0; p < 4; p++) {
        int pp = pbase + p;
        if (pp < rcount) {
            int ch = s0 + pp;
            u64* cdst = (u64*)(c + (size_t)ch * F_N);
            float2 vi_r = u2f(ir[p]),  vi_z = u2f(iz[p]),  vi_n = u2f(in_[p]);
            float2 vh_r = u2f(hr_[p]), vh_z = u2f(hz_[p]), vh_n = u2f(hn_[p]);
#pragma unroll
            for (int half = 0; half < 2; half++) {
                int f = 2 * fy + half;
                float a_ir = half ? vi_r.y : vi_r.x;
                float a_iz = half ? vi_z.y : vi_z.x;
                float a_in = half ? vi_n.y : vi_n.x;
                float a_hr = half ? vh_r.y : vh_r.x;
                float a_hz = half ? vh_z.y : vh_z.x;
                float a_hn = half ? vh_n.y : vh_n.x;
                float r = fast_sigmoid(a_ir + sbi[f] + a_hr);
                float z = fast_sigmoid(a_iz + sbi[32 + f] + a_hz);
                float n = fast_tanh(a_in + sbi[64 + f] + r * (a_hn + sbhn2[f]));
                float hold = sc[f * PS2 + pp];
                hn2[p][half] = n + z * (hold - n);
            }
            cdst[fy] = f2u(hn2[p][0], hn2[p][1]);
        }
    }

    if (!want_table) return;
    __syncthreads();

#pragma unroll
    for (int p = 0; p < 4; p++) {
        int pp = pbase + p;
        if (pp < rcount) {
            sagg[(2 * fy) * PS2 + pp]     = hn2[p][0];
            sagg[(2 * fy + 1) * PS2 + pp] = hn2[p][1];
        }
    }
    for (int i = tid; i < 32 * 48; i += 256) {
        int k = i / 48, po = i % 48;
        swa[k * 48 + po] = f2u(Wi1[(2 * po) * 32 + k], Wi1[(2 * po + 1) * 32 + k]);
    }
    __syncthreads();

    u64 tr[4], tz[4], tn[4];
#pragma unroll
    for (int p = 0; p < 4; p++) { tr[p] = 0ull; tz[p] = 0ull; tn[p] = 0ull; }
#pragma unroll 4
    for (int k = 0; k < 32; k++) {
        const u64* wrow = swa + k * 48;
        u64 wr = wrow[fy];
        u64 wz = wrow[16 + fy];
        u64 wn = wrow[32 + fy];
        float4 ha = *(const float4*)(sagg + k * PS2 + pbase);
        float hv[4] = {ha.x, ha.y, ha.z, ha.w};
#pragma unroll
        for (int p = 0; p < 4; p++) {
            u64 hd = f2u(hv[p], hv[p]);
            tr[p] = ffma2(hd, wr, tr[p]);
            tz[p] = ffma2(hd, wz, tz[p]);
            tn[p] = ffma2(hd, wn, tn[p]);
        }
    }
#pragma unroll
    for (int p = 0; p < 4; p++) {
        int pp = pbase + p;
        if (pp < rcount) {
            u64* trow = (u64*)(g_table + (size_t)(s0 + pp) * 96);
            float2 a0 = u2f(tr[p]), a1 = u2f(tz[p]), a2 = u2f(tn[p]);
            trow[fy]      = f2u(a0.x + sb1[2 * fy],      a0.y + sb1[2 * fy + 1]);
            trow[16 + fy] = f2u(a1.x + sb1[32 + 2 * fy], a1.y + sb1[32 + 2 * fy + 1]);
            trow[32 + fy] = f2u(a2.x + sb1[64 + 2 * fy], a2.y + sb1[64 + 2 * fy + 1]);
        }
    }
}

// ---------------- launch ----------------
extern "C" void kernel_launch(void* const* d_in, const int* in_sizes, int n_in,
                              void* d_out, int out_size)
{
    const float* path_raw    = (const float*)d_in[0];
    const float* channel_raw = (const float*)d_in[1];
    const int*   pci         = (const int*)d_in[2];
    const int*   plen        = (const int*)d_in[3];
    // d_in[4] = num_steps (constant 5)
    const float* Wp  = (const float*)d_in[5];
    const float* bp  = (const float*)d_in[6];
    const float* Wc  = (const float*)d_in[7];
    const float* bc  = (const float*)d_in[8];
    const float* Wi1 = (const float*)d_in[9];
    const float* Wh1 = (const float*)d_in[10];
    const float* bi1 = (const float*)d_in[11];
    const float* bh1 = (const float*)d_in[12];
    const float* Wi2 = (const float*)d_in[13];
    const float* Wh2 = (const float*)d_in[14];
    const float* bi2 = (const float*)d_in[15];
    const float* bh2 = (const float*)d_in[16];

    float* outp = (float*)d_out;
    float* c    = outp + (size_t)P_N * F_N;

    int gridScan = (P_N + STILE - 1) / STILE;     // 1563
    int gridL2   = (C_N + L2TILE - 1) / L2TILE;   // 782

    hist_prefix_kernel<<<PB_BLOCKS, 256>>>(plen);
    scatter_kernel<<<PB_BLOCKS, 256>>>(plen);
    buildinit_gi_kernel<<<PB2 + CB2, 256>>>(plen, pci, path_raw, channel_raw,
                                            Wp, bp, Wc, bc, Wi1, bi1, bh1, c);
    for (int st = 0; st < NSTEPS; st++) {
        scan10_kernel<<<gridScan, 256>>>(Wh1, bh1, (st == NSTEPS - 1) ? outp : nullptr);
        layer2f_kernel<<<gridL2, 256>>>(c, Wi2, Wh2, bi2, bh2, Wi1, bi1, bh1,
                                        (st < NSTEPS - 1) ? 1 : 0);
    }
}

// round 14
// speedup vs baseline: 1.0474x; 1.0474x over previous
#include <cuda_runtime.h>

#define P_N 200000
#define C_N 50000
#define L_N 8
#define F_N 32
#define DIN 64
#define NSTEPS 5

#define PB_BLOCKS ((P_N + 255) / 256)   // histogram blocks
#define BI_TILE 128
#define PB2 ((P_N + BI_TILE - 1) / BI_TILE)   // 1563
#define CB2 ((C_N + BI_TILE - 1) / BI_TILE)   // 391

#define STILE 128                       // scan paths per block
#define SROW 260                        // floats per h-pair row
#define L2T 128                         // layer2 rows per block
#define L2B ((C_N + L2T - 1) / L2T)     // 391
#define XS 132                          // float stride for staging (buildinit + layer2)

typedef unsigned long long u64;

// ---------------- device scratch ----------------
__device__ float g_p[(size_t)P_N * F_N];
__device__ int   g_order[P_N];
__device__ int   g_idx[(size_t)P_N * L_N];
__device__ int   g_len[P_N];
__device__ float g_agg[(size_t)C_N * F_N];
__device__ float g_table[(size_t)C_N * 96];
__device__ int   g_cnt[16];
__device__ int   g_blkhist[PB_BLOCKS * 8];
__device__ int   g_done;

// ---------------- helpers ----------------
__device__ __forceinline__ u64 ffma2(u64 a, u64 b, u64 c) {
    u64 d;
    asm("fma.rn.f32x2 %0, %1, %2, %3;" : "=l"(d) : "l"(a), "l"(b), "l"(c));
    return d;
}
__device__ __forceinline__ float2 u2f(u64 v) {
    float2 r;
    asm("mov.b64 {%0,%1}, %2;" : "=f"(r.x), "=f"(r.y) : "l"(v));
    return r;
}
__device__ __forceinline__ u64 f2u(float a, float b) {
    u64 r;
    asm("mov.b64 %0, {%1,%2};" : "=l"(r) : "f"(a), "f"(b));
    return r;
}

__device__ __forceinline__ float tanh_ap(float x) {
    float y;
    asm("tanh.approx.f32 %0, %1;" : "=f"(y) : "f"(x));
    return y;
}
__device__ __forceinline__ float fast_sigmoid(float v) {
    return fmaf(0.5f, tanh_ap(0.5f * v), 0.5f);
}
__device__ __forceinline__ float fast_tanh(float v) { return tanh_ap(v); }

__device__ __forceinline__ void red_add_v4(float* p, float4 v) {
    asm volatile("red.global.add.v4.f32 [%0], {%1,%2,%3,%4};"
                 :: "l"(p), "f"(v.x), "f"(v.y), "f"(v.z), "f"(v.w) : "memory");
}
__device__ __forceinline__ u64 ldg64(const u64* p) {
    u64 v;
    asm("ld.global.nc.b64 %0, [%1];" : "=l"(v) : "l"(p));
    return v;
}

// ---------------- fused hist + prefix (last-block-done) ----------------
__global__ void __launch_bounds__(256) hist_prefix_kernel(const int* __restrict__ plen) {
    __shared__ int lh[8];
    __shared__ int slast;
    int tid = threadIdx.x;
    if (tid < 8) lh[tid] = 0;
    __syncthreads();
    int i = blockIdx.x * 256 + tid;
    if (i < P_N) {
        int b = plen[i]; b = b < 0 ? 0 : (b > 7 ? 7 : b);
        atomicAdd(&lh[b], 1);
    }
    __syncthreads();
    if (tid < 8) g_blkhist[blockIdx.x * 8 + tid] = lh[tid];
    __threadfence();
    if (tid == 0) {
        int t = atomicAdd(&g_done, 1);
        slast = (t == gridDim.x - 1) ? 1 : 0;
    }
    __syncthreads();
    if (slast) {
        __threadfence();
        int local[8] = {0, 0, 0, 0, 0, 0, 0, 0};
        for (int j = tid; j < PB_BLOCKS; j += 256) {
#pragma unroll
            for (int b = 0; b < 8; b++) local[b] += g_blkhist[j * 8 + b];
        }
        if (tid < 8) lh[tid] = 0;
        __syncthreads();
#pragma unroll
        for (int b = 0; b < 8; b++) atomicAdd(&lh[b], local[b]);
        __syncthreads();
        if (tid == 0) {
            int acc = 0;
#pragma unroll
            for (int b = 7; b >= 0; b--) { int cv = lh[b]; g_cnt[b] = acc; acc += cv; }
            g_done = 0;
        }
    }
}

__global__ void __launch_bounds__(256) scatter_kernel(const int* __restrict__ plen) {
    int i = blockIdx.x * 256 + threadIdx.x;
    if (i < P_N) {
        int b = plen[i]; b = b < 0 ? 0 : (b > 7 ? 7 : b);
        int pos = atomicAdd(&g_cnt[b], 1);
        g_order[pos] = i;
    }
}

// ---------------- tiled buildinit: paths (init p) + channels (init c + gi1 table) ----------------
__global__ void __launch_bounds__(256, 2) buildinit_gi_kernel(const int* __restrict__ plen,
                                                              const int* __restrict__ pci,
                                                              const float* __restrict__ praw,
                                                              const float* __restrict__ craw,
                                                              const float* __restrict__ Wp,
                                                              const float* __restrict__ bp,
                                                              const float* __restrict__ Wc,
                                                              const float* __restrict__ bc,
                                                              const float* __restrict__ Wi1,
                                                              const float* __restrict__ bi1,
                                                              const float* __restrict__ bh1,
                                                              float* __restrict__ c)
{
    __shared__ __align__(16) float sxx[64 * XS];
    __shared__ __align__(16) u64   sww[32 * 48];
    __shared__ int   sord[BI_TILE];
    __shared__ float sb[32];
    __shared__ float sb1[96];

    int tid = threadIdx.x;
    bool isPath = blockIdx.x < PB2;
    int s0 = isPath ? blockIdx.x * BI_TILE : (blockIdx.x - PB2) * BI_TILE;
    int rcount = isPath ? min(BI_TILE, P_N - s0) : min(BI_TILE, C_N - s0);
    const float* W = isPath ? Wp : Wc;
    const float* b = isPath ? bp : bc;
    const float* xsrc = isPath ? praw : craw;

    for (int i = tid; i < 64 * 16; i += 256) {
        int d = i >> 4, o = i & 15;
        const float2* wp2 = (const float2*)(W + d * 32);
        float2 w = wp2[o];
        sww[d * 16 + o] = f2u(w.x, w.y);
    }
    if (tid < 32) sb[tid] = b[tid];
    if (!isPath && tid < 96) sb1[tid] = bi1[tid] + (tid < 64 ? bh1[tid] : 0.0f);

    if (isPath) {
        if (tid < BI_TILE) {
            int row = s0 + tid;
            if (row < P_N) {
                int sr = g_order[row];
                sord[tid] = sr;
                g_len[row] = plen[sr];
                const int4* si = (const int4*)(pci + (size_t)sr * L_N);
                int4* di = (int4*)(g_idx + (size_t)row * L_N);
                di[0] = si[0]; di[1] = si[1];
            }
        }
    }
    __syncthreads();

    for (int i = tid; i < rcount * 16; i += 256) {
        int r = i >> 4, q = i & 15;
        int sr = isPath ? sord[r] : (s0 + r);
        float4 v = ((const float4*)(xsrc + (size_t)sr * DIN))[q];
        sxx[(4 * q + 0) * XS + r] = v.x;
        sxx[(4 * q + 1) * XS + r] = v.y;
        sxx[(4 * q + 2) * XS + r] = v.z;
        sxx[(4 * q + 3) * XS + r] = v.w;
    }
    __syncthreads();

    int px = tid >> 4, fy = tid & 15;
    int pbase = px * 8;

    u64 acc[8];
#pragma unroll
    for (int p = 0; p < 8; p++) acc[p] = 0ull;
#pragma unroll 4
    for (int k = 0; k < 64; k++) {
        u64 w = sww[k * 16 + fy];
        const float4* xr = (const float4*)(sxx + k * XS + pbase);
        float4 a = xr[0], bq = xr[1];
        float xv[8] = {a.x, a.y, a.z, a.w, bq.x, bq.y, bq.z, bq.w};
#pragma unroll
        for (int p = 0; p < 8; p++)
            acc[p] = ffma2(f2u(xv[p], xv[p]), w, acc[p]);
    }

    float* dst = isPath ? g_p : c;
    float cres[8][2];
    float b0 = sb[2 * fy], b1 = sb[2 * fy + 1];
#pragma unroll
    for (int p = 0; p < 8; p++) {
        int pp = pbase + p;
        float2 v = u2f(acc[p]);
        float r0 = fmaxf(v.x + b0, 0.0f);
        float r1 = fmaxf(v.y + b1, 0.0f);
        cres[p][0] = r0; cres[p][1] = r1;
        if (pp < rcount)
            ((u64*)(dst + (size_t)(s0 + pp) * F_N))[fy] = f2u(r0, r1);
    }

    if (isPath) return;

    __syncthreads();
    for (int i = tid; i < rcount * 8; i += 256)
        ((float4*)(g_agg + (size_t)s0 * F_N))[i] = make_float4(0.f, 0.f, 0.f, 0.f);
#pragma unroll
    for (int p = 0; p < 8; p++) {
        int pp = pbase + p;
        if (pp < rcount) {
            sxx[(2 * fy) * XS + pp]     = cres[p][0];
            sxx[(2 * fy + 1) * XS + pp] = cres[p][1];
        }
    }
    for (int i = tid; i < 32 * 48; i += 256) {
        int k = i / 48, po = i % 48;
        sww[k * 48 + po] = f2u(Wi1[(2 * po) * 32 + k], Wi1[(2 * po + 1) * 32 + k]);
    }
    __syncthreads();

    u64 tr[8], tz[8], tn[8];
#pragma unroll
    for (int p = 0; p < 8; p++) { tr[p] = 0ull; tz[p] = 0ull; tn[p] = 0ull; }
#pragma unroll 4
    for (int k = 0; k < 32; k++) {
        const u64* wrow = sww + k * 48;
        u64 wr = wrow[fy], wz = wrow[16 + fy], wn = wrow[32 + fy];
        const float4* xr = (const float4*)(sxx + k * XS + pbase);
        float4 a = xr[0], bq = xr[1];
        float xv[8] = {a.x, a.y, a.z, a.w, bq.x, bq.y, bq.z, bq.w};
#pragma unroll
        for (int p = 0; p < 8; p++) {
            u64 d = f2u(xv[p], xv[p]);
            tr[p] = ffma2(d, wr, tr[p]);
            tz[p] = ffma2(d, wz, tz[p]);
            tn[p] = ffma2(d, wn, tn[p]);
        }
    }
    float br0 = sb1[2 * fy],      br1 = sb1[2 * fy + 1];
    float bz0 = sb1[32 + 2 * fy], bz1 = sb1[32 + 2 * fy + 1];
    float bn0 = sb1[64 + 2 * fy], bn1 = sb1[64 + 2 * fy + 1];
#pragma unroll
    for (int p = 0; p < 8; p++) {
        int pp = pbase + p;
        if (pp < rcount) {
            u64* trow = (u64*)(g_table + (size_t)(s0 + pp) * 96);
            float2 a0 = u2f(tr[p]), a1 = u2f(tz[p]), a2 = u2f(tn[p]);
            trow[fy]      = f2u(a0.x + br0, a0.y + br1);
            trow[16 + fy] = f2u(a1.x + bz0, a1.y + bz1);
            trow[32 + fy] = f2u(a2.x + bn0, a2.y + bn1);
        }
    }
}

// ---------------- scan10: warp-autonomous, pairwise-prefetch epilogue ----------------
__global__ void __launch_bounds__(256, 2) scan10_kernel(const float* __restrict__ Wh,
                                                        const float* __restrict__ bh,
                                                        float* __restrict__ final_out)
{
    __shared__ __align__(16) u64   sww[32 * 48];
    __shared__ __align__(16) float shf[16 * SROW];
    __shared__ unsigned short sidx[STILE * L_N];
    __shared__ short slen[STILE];
    __shared__ float sbhn[32];

    int tid = threadIdx.x;
    int s0 = blockIdx.x * STILE;
    int pcount = min(STILE, P_N - s0);

    for (int i = tid; i < 32 * 48; i += 256) {
        int k = i / 48, po = i % 48;
        sww[k * 48 + po] = f2u(Wh[(2 * po) * 32 + k], Wh[(2 * po + 1) * 32 + k]);
    }
    if (tid < 32) sbhn[tid] = bh[64 + tid];
    if (tid < STILE) slen[tid] = (tid < pcount) ? (short)g_len[s0 + tid] : (short)-1;
    for (int i = tid; i < STILE * L_N; i += 256)
        sidx[i] = (i < pcount * L_N) ? (unsigned short)g_idx[(size_t)s0 * L_N + i] : (unsigned short)0;
    if (pcount < STILE) {
        for (int i = tid; i < 16 * SROW; i += 256) shf[i] = 0.0f;
        __syncthreads();
    }
    for (int i = tid; i < pcount * 8; i += 256) {
        int p = i >> 3, kq = i & 7;
        float4 v = ((const float4*)(g_p + (size_t)s0 * F_N))[i];
        float* r0 = &shf[(2 * kq) * SROW + 2 * p];
        r0[0] = v.x; r0[1] = v.y;
        float* r1 = &shf[(2 * kq + 1) * SROW + 2 * p];
        r1[0] = v.z; r1[1] = v.w;
    }
    __syncthreads();

    int px = tid >> 4;
    int fy = tid & 15;
    int pbase = px * 8;
    int wfirst = (tid >> 5) * 16;
    int tmax = slen[wfirst];

    for (int t = 0; t <= tmax; t++) {
        u64 ar[8], az[8], an[8];
#pragma unroll
        for (int p = 0; p < 8; p++) { ar[p] = 0ull; az[p] = 0ull; an[p] = 0ull; }

#pragma unroll 4
        for (int j = 0; j < 16; j++) {
            const u64* w0 = sww + (2 * j) * 48;
            const u64* w1 = sww + (2 * j + 1) * 48;
            u64 wr0 = w0[fy], wz0 = w0[16 + fy], wn0 = w0[32 + fy];
            u64 wr1 = w1[fy], wz1 = w1[16 + fy], wn1 = w1[32 + fy];
            const float4* hq = (const float4*)(shf + j * SROW + 2 * pbase);
            float4 q0 = hq[0], q1 = hq[1], q2 = hq[2], q3 = hq[3];
            float qe[8] = {q0.x, q0.z, q1.x, q1.z, q2.x, q2.z, q3.x, q3.z};
            float qo[8] = {q0.y, q0.w, q1.y, q1.w, q2.y, q2.w, q3.y, q3.w};
#pragma unroll
            for (int p = 0; p < 8; p++) {
                u64 he = f2u(qe[p], qe[p]);
                ar[p] = ffma2(he, wr0, ar[p]);
                az[p] = ffma2(he, wz0, az[p]);
                an[p] = ffma2(he, wn0, an[p]);
                u64 ho = f2u(qo[p], qo[p]);
                ar[p] = ffma2(ho, wr1, ar[p]);
                az[p] = ffma2(ho, wz1, az[p]);
                an[p] = ffma2(ho, wn1, an[p]);
            }
        }
        __syncwarp();

        {
            u64 ga0, ga1, ga2, gb0, gb1, gb2;
            {
                int cha = sidx[(pbase + 0) * L_N + t];
                const u64* tga = (const u64*)(g_table + (size_t)cha * 96);
                ga0 = ldg64(tga + fy); ga1 = ldg64(tga + 16 + fy); ga2 = ldg64(tga + 32 + fy);
                int chb = sidx[(pbase + 1) * L_N + t];
                const u64* tgb = (const u64*)(g_table + (size_t)chb * 96);
                gb0 = ldg64(tgb + fy); gb1 = ldg64(tgb + 16 + fy); gb2 = ldg64(tgb + 32 + fy);
            }
#pragma unroll
            for (int pr = 0; pr < 4; pr++) {
                u64 na0 = 0, na1 = 0, na2 = 0, nb0 = 0, nb1 = 0, nb2 = 0;
                if (pr < 3) {
                    int cha = sidx[(pbase + 2 * pr + 2) * L_N + t];
                    const u64* tga = (const u64*)(g_table + (size_t)cha * 96);
                    na0 = ldg64(tga + fy); na1 = ldg64(tga + 16 + fy); na2 = ldg64(tga + 32 + fy);
                    int chb = sidx[(pbase + 2 * pr + 3) * L_N + t];
                    const u64* tgb = (const u64*)(g_table + (size_t)chb * 96);
                    nb0 = ldg64(tgb + fy); nb1 = ldg64(tgb + 16 + fy); nb2 = ldg64(tgb + 32 + fy);
                }
#pragma unroll
                for (int s = 0; s < 2; s++) {
                    int pp = pbase + 2 * pr + s;
                    u64 cg0 = s ? gb0 : ga0;
                    u64 cg1 = s ? gb1 : ga1;
                    u64 cg2 = s ? gb2 : ga2;
                    int p = 2 * pr + s;
                    bool active = (t <= slen[pp]);
                    float2 gr = u2f(cg0), gz = u2f(cg1), gn = u2f(cg2);
                    float2 vr = u2f(ar[p]), vz = u2f(az[p]), vn = u2f(an[p]);
                    float2 hold = *(const float2*)(shf + fy * SROW + 2 * pp);
                    float h0, h1;
                    {
                        float r = fast_sigmoid(gr.x + vr.x);
                        float z = fast_sigmoid(gz.x + vz.x);
                        float n = fast_tanh(gn.x + r * (vn.x + sbhn[2 * fy]));
                        h0 = n + z * (hold.x - n);
                    }
                    {
                        float r = fast_sigmoid(gr.y + vr.y);
                        float z = fast_sigmoid(gz.y + vz.y);
                        float n = fast_tanh(gn.y + r * (vn.y + sbhn[2 * fy + 1]));
                        h1 = n + z * (hold.y - n);
                    }
                    if (active)
                        *(float2*)(shf + fy * SROW + 2 * pp) = make_float2(h0, h1);
                }
                ga0 = na0; ga1 = na1; ga2 = na2;
                gb0 = nb0; gb1 = nb1; gb2 = nb2;
            }
        }
        __syncwarp();
    }

    __syncthreads();

    int p = tid & (STILE - 1);
    int kc = tid >> 7;
    if (p < pcount) {
        float v[16];
#pragma unroll
        for (int j = 0; j < 16; j++) {
            int f = kc * 16 + j;
            v[j] = shf[(f >> 1) * SROW + 2 * p + (f & 1)];
        }
        float4* dst;
        if (final_out) {
            int ord = g_order[s0 + p];
            dst = (float4*)(final_out + (size_t)ord * F_N + kc * 16);
        } else {
            dst = (float4*)(g_p + (size_t)(s0 + p) * F_N + kc * 16);
        }
#pragma unroll
        for (int q = 0; q < 4; q++)
            dst[q] = make_float4(v[4 * q], v[4 * q + 1], v[4 * q + 2], v[4 * q + 3]);
        int ln = slen[p];
#pragma unroll 1
        for (int t = 0; t <= ln; t++) {
            int ch = sidx[p * L_N + t];
            float* base = g_agg + (size_t)ch * F_N + kc * 16;
            red_add_v4(base + 0,  make_float4(v[0],  v[1],  v[2],  v[3]));
            red_add_v4(base + 4,  make_float4(v[4],  v[5],  v[6],  v[7]));
            red_add_v4(base + 8,  make_float4(v[8],  v[9],  v[10], v[11]));
            red_add_v4(base + 12, make_float4(v[12], v[13], v[14], v[15]));
        }
    }
}

// ---------------- layer2g: 128 rows/block (1.3 waves), fused gi2+gh2, gi1 table ----------------
// 256 thr = 16(px) x 16(fy), thread tile 8 rows x 6 outs per accumulator set.
__global__ void __launch_bounds__(256, 2) layer2g_kernel(float* __restrict__ c,
                                                         const float* __restrict__ Wi2,
                                                         const float* __restrict__ Wh2,
                                                         const float* __restrict__ bi2,
                                                         const float* __restrict__ bh2,
                                                         const float* __restrict__ Wi1,
                                                         const float* __restrict__ bi1,
                                                         const float* __restrict__ bh1,
                                                         int want_table)
{
    __shared__ __align__(16) u64   swa[32 * 48];     // Wi2 pairs -> Wi1 pairs
    __shared__ __align__(16) u64   swh[32 * 48];     // Wh2 pairs
    __shared__ __align__(16) float sagg[32 * XS];    // agg staging -> cnew staging
    __shared__ __align__(16) float sc[32 * XS];      // c staging (hold values)
    __shared__ float sbi[96];
    __shared__ float sbhn2[32];
    __shared__ float sb1[96];

    int tid = threadIdx.x;
    int s0 = blockIdx.x * L2T;
    int rcount = min(L2T, C_N - s0);

    for (int i = tid; i < 32 * 48; i += 256) {
        int k = i / 48, po = i % 48;
        swa[k * 48 + po] = f2u(Wi2[(2 * po) * 32 + k], Wi2[(2 * po + 1) * 32 + k]);
        swh[k * 48 + po] = f2u(Wh2[(2 * po) * 32 + k], Wh2[(2 * po + 1) * 32 + k]);
    }
    if (tid < 96) {
        sbi[tid] = bi2[tid] + (tid < 64 ? bh2[tid] : 0.0f);
        sb1[tid] = bi1[tid] + (tid < 64 ? bh1[tid] : 0.0f);
    }
    if (tid < 32) sbhn2[tid] = bh2[64 + tid];
    if (rcount < L2T) {
        for (int i = tid; i < 32 * L2T; i += 256) {
            int p = i & (L2T - 1);
            if (p >= rcount) { sagg[(i >> 7) * XS + p] = 0.0f; sc[(i >> 7) * XS + p] = 0.0f; }
        }
    }
    for (int i = tid; i < rcount * 8; i += 256) {
        int p = i >> 3, kq = i & 7;
        float4 va = ((const float4*)(g_agg + (size_t)s0 * F_N))[i];
        sagg[(4 * kq + 0) * XS + p] = va.x;
        sagg[(4 * kq + 1) * XS + p] = va.y;
        sagg[(4 * kq + 2) * XS + p] = va.z;
        sagg[(4 * kq + 3) * XS + p] = va.w;
        ((float4*)(g_agg + (size_t)s0 * F_N))[i] = make_float4(0.f, 0.f, 0.f, 0.f);
        float4 vc = ((const float4*)(c + (size_t)s0 * F_N))[i];
        sc[(4 * kq + 0) * XS + p] = vc.x;
        sc[(4 * kq + 1) * XS + p] = vc.y;
        sc[(4 * kq + 2) * XS + p] = vc.z;
        sc[(4 * kq + 3) * XS + p] = vc.w;
    }
    __syncthreads();

    int px = tid >> 4, fy = tid & 15;
    int pbase = px * 8;

    // phase A: gi2 = agg @ Wi2^T
    u64 ir[8], iz[8], in_[8];
#pragma unroll
    for (int p = 0; p < 8; p++) { ir[p] = 0ull; iz[p] = 0ull; in_[p] = 0ull; }
#pragma unroll 4
    for (int k = 0; k < 32; k++) {
        const u64* wA = swa + k * 48;
        u64 war = wA[fy], waz = wA[16 + fy], wan = wA[32 + fy];
        const float4* xr = (const float4*)(sagg + k * XS + pbase);
        float4 a = xr[0], bq = xr[1];
        float av[8] = {a.x, a.y, a.z, a.w, bq.x, bq.y, bq.z, bq.w};
#pragma unroll
        for (int p = 0; p < 8; p++) {
            u64 da = f2u(av[p], av[p]);
            ir[p]  = ffma2(da, war, ir[p]);
            iz[p]  = ffma2(da, waz, iz[p]);
            in_[p] = ffma2(da, wan, in_[p]);
        }
    }

    // phase B: gh2 = c @ Wh2^T
    u64 hr_[8], hz_[8], hn_[8];
#pragma unroll
    for (int p = 0; p < 8; p++) { hr_[p] = 0ull; hz_[p] = 0ull; hn_[p] = 0ull; }
#pragma unroll 4
    for (int k = 0; k < 32; k++) {
        const u64* wH = swh + k * 48;
        u64 whr = wH[fy], whz = wH[16 + fy], whn = wH[32 + fy];
        const float4* xr = (const float4*)(sc + k * XS + pbase);
        float4 a = xr[0], bq = xr[1];
        float cv[8] = {a.x, a.y, a.z, a.w, bq.x, bq.y, bq.z, bq.w};
#pragma unroll
        for (int p = 0; p < 8; p++) {
            u64 dc = f2u(cv[p], cv[p]);
            hr_[p] = ffma2(dc, whr, hr_[p]);
            hz_[p] = ffma2(dc, whz, hz_[p]);
            hn_[p] = ffma2(dc, whn, hn_[p]);
        }
    }

    // epilogue: cnew; write global c
    float hn2[8][2];
#pragma unroll
    for (int p = 0; p < 8; p++) {
        int pp = pbase + p;
        if (pp < rcount) {
            int ch = s0 + pp;
            u64* cdst = (u64*)(c + (size_t)ch * F_N);
            float2 vi_r = u2f(ir[p]),  vi_z = u2f(iz[p]),  vi_n = u2f(in_[p]);
            float2 vh_r = u2f(hr_[p]), vh_z = u2f(hz_[p]), vh_n = u2f(hn_[p]);
#pragma unroll
            for (int half = 0; half < 2; half++) {
                int f = 2 * fy + half;
                float a_ir = half ? vi_r.y : vi_r.x;
                float a_iz = half ? vi_z.y : vi_z.x;
                float a_in = half ? vi_n.y : vi_n.x;
                float a_hr = half ? vh_r.y : vh_r.x;
                float a_hz = half ? vh_z.y : vh_z.x;
                float a_hn = half ? vh_n.y : vh_n.x;
                float r = fast_sigmoid(a_ir + sbi[f] + a_hr);
                float z = fast_sigmoid(a_iz + sbi[32 + f] + a_hz);
                float n = fast_tanh(a_in + sbi[64 + f] + r * (a_hn + sbhn2[f]));
                float hold = sc[f * XS + pp];
                hn2[p][half] = n + z * (hold - n);
            }
            cdst[fy] = f2u(hn2[p][0], hn2[p][1]);
        }
    }

    if (!want_table) return;
    __syncthreads();   // all k-loop + epilogue smem reads done before overwrites

    // restage: sagg <- cnew, swa <- Wi1 pairs
#pragma unroll
    for (int p = 0; p < 8; p++) {
        int pp = pbase + p;
        if (pp < rcount) {
            sagg[(2 * fy) * XS + pp]     = hn2[p][0];
            sagg[(2 * fy + 1) * XS + pp] = hn2[p][1];
        }
    }
    for (int i = tid; i < 32 * 48; i += 256) {
        int k = i / 48, po = i % 48;
        swa[k * 48 + po] = f2u(Wi1[(2 * po) * 32 + k], Wi1[(2 * po + 1) * 32 + k]);
    }
    __syncthreads();

    u64 tr[8], tz[8], tn[8];
#pragma unroll
    for (int p = 0; p < 8; p++) { tr[p] = 0ull; tz[p] = 0ull; tn[p] = 0ull; }
#pragma unroll 4
    for (int k = 0; k < 32; k++) {
        const u64* wrow = swa + k * 48;
        u64 wr = wrow[fy], wz = wrow[16 + fy], wn = wrow[32 + fy];
        const float4* xr = (const float4*)(sagg + k * XS + pbase);
        float4 a = xr[0], bq = xr[1];
        float hv[8] = {a.x, a.y, a.z, a.w, bq.x, bq.y, bq.z, bq.w};
#pragma unroll
        for (int p = 0; p < 8; p++) {
            u64 hd = f2u(hv[p], hv[p]);
            tr[p] = ffma2(hd, wr, tr[p]);
            tz[p] = ffma2(hd, wz, tz[p]);
            tn[p] = ffma2(hd, wn, tn[p]);
        }
    }
    float br0 = sb1[2 * fy],      br1 = sb1[2 * fy + 1];
    float bz0 = sb1[32 + 2 * fy], bz1 = sb1[32 + 2 * fy + 1];
    float bn0 = sb1[64 + 2 * fy], bn1 = sb1[64 + 2 * fy + 1];
#pragma unroll
    for (int p = 0; p < 8; p++) {
        int pp = pbase + p;
        if (pp < rcount) {
            u64* trow = (u64*)(g_table + (size_t)(s0 + pp) * 96);
            float2 a0 = u2f(tr[p]), a1 = u2f(tz[p]), a2 = u2f(tn[p]);
            trow[fy]      = f2u(a0.x + br0, a0.y + br1);
            trow[16 + fy] = f2u(a1.x + bz0, a1.y + bz1);
            trow[32 + fy] = f2u(a2.x + bn0, a2.y + bn1);
        }
    }
}

// ---------------- launch ----------------
extern "C" void kernel_launch(void* const* d_in, const int* in_sizes, int n_in,
                              void* d_out, int out_size)
{
    const float* path_raw    = (const float*)d_in[0];
    const float* channel_raw = (const float*)d_in[1];
    const int*   pci         = (const int*)d_in[2];
    const int*   plen        = (const int*)d_in[3];
    // d_in[4] = num_steps (constant 5)
    const float* Wp  = (const float*)d_in[5];
    const float* bp  = (const float*)d_in[6];
    const float* Wc  = (const float*)d_in[7];
    const float* bc  = (const float*)d_in[8];
    const float* Wi1 = (const float*)d_in[9];
    const float* Wh1 = (const float*)d_in[10];
    const float* bi1 = (const float*)d_in[11];
    const float* bh1 = (const float*)d_in[12];
    const float* Wi2 = (const float*)d_in[13];
    const float* Wh2 = (const float*)d_in[14];
    const float* bi2 = (const float*)d_in[15];
    const float* bh2 = (const float*)d_in[16];

    float* outp = (float*)d_out;
    float* c    = outp + (size_t)P_N * F_N;

    int gridScan = (P_N + STILE - 1) / STILE;     // 1563

    hist_prefix_kernel<<<PB_BLOCKS, 256>>>(plen);
    scatter_kernel<<<PB_BLOCKS, 256>>>(plen);
    buildinit_gi_kernel<<<PB2 + CB2, 256>>>(plen, pci, path_raw, channel_raw,
                                            Wp, bp, Wc, bc, Wi1, bi1, bh1, c);
    for (int st = 0; st < NSTEPS; st++) {
        scan10_kernel<<<gridScan, 256>>>(Wh1, bh1, (st == NSTEPS - 1) ? outp : nullptr);
        layer2g_kernel<<<L2B, 256>>>(c, Wi2, Wh2, bi2, bh2, Wi1, bi1, bh1,
                                     (st < NSTEPS - 1) ? 1 : 0);
    }
}

// round 15
// speedup vs baseline: 1.0620x; 1.0140x over previous
#include <cuda_runtime.h>

#define P_N 200000
#define C_N 50000
#define L_N 8
#define F_N 32
#define DIN 64
#define NSTEPS 5

#define PB_BLOCKS ((P_N + 255) / 256)   // histogram blocks (782)
#define BI_TILE 128
#define PB2 ((P_N + BI_TILE - 1) / BI_TILE)   // 1563
#define CB2 ((C_N + BI_TILE - 1) / BI_TILE)   // 391

#define STILE 128                       // scan paths per block
#define SROW 260                        // floats per h-pair row
#define L2T 128                         // layer2 rows per block
#define L2B ((C_N + L2T - 1) / L2T)     // 391
#define XS 132                          // float stride for staging

typedef unsigned long long u64;

// ---------------- device scratch ----------------
__device__ float g_p[(size_t)P_N * F_N];
__device__ int   g_order[P_N];
__device__ int   g_idx[(size_t)P_N * L_N];
__device__ int   g_len[P_N];
__device__ float g_agg[(size_t)C_N * F_N];
__device__ float g_table[(size_t)C_N * 96];
__device__ int   g_blkhist[PB_BLOCKS * 8];
__device__ int   g_blkoff[PB_BLOCKS * 8];
__device__ int   g_done;

// ---------------- helpers ----------------
__device__ __forceinline__ u64 ffma2(u64 a, u64 b, u64 c) {
    u64 d;
    asm("fma.rn.f32x2 %0, %1, %2, %3;" : "=l"(d) : "l"(a), "l"(b), "l"(c));
    return d;
}
__device__ __forceinline__ float2 u2f(u64 v) {
    float2 r;
    asm("mov.b64 {%0,%1}, %2;" : "=f"(r.x), "=f"(r.y) : "l"(v));
    return r;
}
__device__ __forceinline__ u64 f2u(float a, float b) {
    u64 r;
    asm("mov.b64 %0, {%1,%2};" : "=l"(r) : "f"(a), "f"(b));
    return r;
}

__device__ __forceinline__ float tanh_ap(float x) {
    float y;
    asm("tanh.approx.f32 %0, %1;" : "=f"(y) : "f"(x));
    return y;
}
__device__ __forceinline__ float fast_sigmoid(float v) {
    return fmaf(0.5f, tanh_ap(0.5f * v), 0.5f);
}
__device__ __forceinline__ float fast_tanh(float v) { return tanh_ap(v); }

__device__ __forceinline__ void red_add_v4(float* p, float4 v) {
    asm volatile("red.global.add.v4.f32 [%0], {%1,%2,%3,%4};"
                 :: "l"(p), "f"(v.x), "f"(v.y), "f"(v.z), "f"(v.w) : "memory");
}
__device__ __forceinline__ u64 ldg64(const u64* p) {
    u64 v;
    asm("ld.global.nc.b64 %0, [%1];" : "=l"(v) : "l"(p));
    return v;
}

// ---------------- hist + per-block offsets (last-block-done, NO global atomics later) ----------------
__global__ void __launch_bounds__(256) hist_prefix_kernel(const int* __restrict__ plen) {
    __shared__ int lh[8];
    __shared__ int slast;
    int tid = threadIdx.x;
    if (tid < 8) lh[tid] = 0;
    __syncthreads();
    int i = blockIdx.x * 256 + tid;
    if (i < P_N) {
        int b = plen[i]; b = b < 0 ? 0 : (b > 7 ? 7 : b);
        atomicAdd(&lh[b], 1);
    }
    __syncthreads();
    if (tid < 8) g_blkhist[blockIdx.x * 8 + tid] = lh[tid];
    __threadfence();
    if (tid == 0) {
        int t = atomicAdd(&g_done, 1);
        slast = (t == gridDim.x - 1) ? 1 : 0;
    }
    __syncthreads();
    if (slast) {
        __threadfence();
        // bucket totals
        int local[8] = {0, 0, 0, 0, 0, 0, 0, 0};
        for (int j = tid; j < PB_BLOCKS; j += 256) {
#pragma unroll
            for (int b = 0; b < 8; b++) local[b] += g_blkhist[j * 8 + b];
        }
        if (tid < 8) lh[tid] = 0;
        __syncthreads();
#pragma unroll
        for (int b = 0; b < 8; b++) atomicAdd(&lh[b], local[b]);
        __syncthreads();
        __shared__ int base[8];
        if (tid == 0) {
            int acc = 0;
#pragma unroll
            for (int b = 7; b >= 0; b--) { int cv = lh[b]; base[b] = acc; acc += cv; }
            g_done = 0;
        }
        __syncthreads();
        // per-block exclusive scan per bucket: 8 threads, serial over blocks
        if (tid < 8) {
            int b = tid;
            int acc = base[b];
            for (int j = 0; j < PB_BLOCKS; j++) {
                g_blkoff[j * 8 + b] = acc;
                acc += g_blkhist[j * 8 + b];
            }
        }
    }
}

// scatter: ranks from per-block offsets + block-local smem atomics (no global atomics)
__global__ void __launch_bounds__(256) scatter_kernel(const int* __restrict__ plen) {
    __shared__ int loff[8];
    int tid = threadIdx.x;
    if (tid < 8) loff[tid] = g_blkoff[blockIdx.x * 8 + tid];
    __syncthreads();
    int i = blockIdx.x * 256 + tid;
    if (i < P_N) {
        int b = plen[i]; b = b < 0 ? 0 : (b > 7 ? 7 : b);
        int pos = atomicAdd(&loff[b], 1);
        g_order[pos] = i;
    }
}

// ---------------- tiled buildinit: paths (init p) + channels (init c + gi1 table) ----------------
__global__ void __launch_bounds__(256, 2) buildinit_gi_kernel(const int* __restrict__ plen,
                                                              const int* __restrict__ pci,
                                                              const float* __restrict__ praw,
                                                              const float* __restrict__ craw,
                                                              const float* __restrict__ Wp,
                                                              const float* __restrict__ bp,
                                                              const float* __restrict__ Wc,
                                                              const float* __restrict__ bc,
                                                              const float* __restrict__ Wi1,
                                                              const float* __restrict__ bi1,
                                                              const float* __restrict__ bh1,
                                                              float* __restrict__ c)
{
    __shared__ __align__(16) float sxx[64 * XS];
    __shared__ __align__(16) u64   sww[32 * 48];
    __shared__ int   sord[BI_TILE];
    __shared__ float sb[32];
    __shared__ float sb1[96];

    int tid = threadIdx.x;
    bool isPath = blockIdx.x < PB2;
    int s0 = isPath ? blockIdx.x * BI_TILE : (blockIdx.x - PB2) * BI_TILE;
    int rcount = isPath ? min(BI_TILE, P_N - s0) : min(BI_TILE, C_N - s0);
    const float* W = isPath ? Wp : Wc;
    const float* b = isPath ? bp : bc;
    const float* xsrc = isPath ? praw : craw;

    for (int i = tid; i < 64 * 16; i += 256) {
        int d = i >> 4, o = i & 15;
        const float2* wp2 = (const float2*)(W + d * 32);
        float2 w = wp2[o];
        sww[d * 16 + o] = f2u(w.x, w.y);
    }
    if (tid < 32) sb[tid] = b[tid];
    if (!isPath && tid < 96) sb1[tid] = bi1[tid] + (tid < 64 ? bh1[tid] : 0.0f);

    if (isPath) {
        if (tid < BI_TILE) {
            int row = s0 + tid;
            if (row < P_N) {
                int sr = g_order[row];
                sord[tid] = sr;
                g_len[row] = plen[sr];
                const int4* si = (const int4*)(pci + (size_t)sr * L_N);
                int4* di = (int4*)(g_idx + (size_t)row * L_N);
                di[0] = si[0]; di[1] = si[1];
            }
        }
    }
    __syncthreads();

    for (int i = tid; i < rcount * 16; i += 256) {
        int r = i >> 4, q = i & 15;
        int sr = isPath ? sord[r] : (s0 + r);
        float4 v = ((const float4*)(xsrc + (size_t)sr * DIN))[q];
        sxx[(4 * q + 0) * XS + r] = v.x;
        sxx[(4 * q + 1) * XS + r] = v.y;
        sxx[(4 * q + 2) * XS + r] = v.z;
        sxx[(4 * q + 3) * XS + r] = v.w;
    }
    __syncthreads();

    int px = tid >> 4, fy = tid & 15;
    int pbase = px * 8;

    u64 acc[8];
#pragma unroll
    for (int p = 0; p < 8; p++) acc[p] = 0ull;
#pragma unroll 4
    for (int k = 0; k < 64; k++) {
        u64 w = sww[k * 16 + fy];
        const float4* xr = (const float4*)(sxx + k * XS + pbase);
        float4 a = xr[0], bq = xr[1];
        float xv[8] = {a.x, a.y, a.z, a.w, bq.x, bq.y, bq.z, bq.w};
#pragma unroll
        for (int p = 0; p < 8; p++)
            acc[p] = ffma2(f2u(xv[p], xv[p]), w, acc[p]);
    }

    float* dst = isPath ? g_p : c;
    float cres[8][2];
    float b0 = sb[2 * fy], b1 = sb[2 * fy + 1];
#pragma unroll
    for (int p = 0; p < 8; p++) {
        int pp = pbase + p;
        float2 v = u2f(acc[p]);
        float r0 = fmaxf(v.x + b0, 0.0f);
        float r1 = fmaxf(v.y + b1, 0.0f);
        cres[p][0] = r0; cres[p][1] = r1;
        if (pp < rcount)
            ((u64*)(dst + (size_t)(s0 + pp) * F_N))[fy] = f2u(r0, r1);
    }

    if (isPath) return;

    __syncthreads();
    for (int i = tid; i < rcount * 8; i += 256)
        ((float4*)(g_agg + (size_t)s0 * F_N))[i] = make_float4(0.f, 0.f, 0.f, 0.f);
#pragma unroll
    for (int p = 0; p < 8; p++) {
        int pp = pbase + p;
        if (pp < rcount) {
            sxx[(2 * fy) * XS + pp]     = cres[p][0];
            sxx[(2 * fy + 1) * XS + pp] = cres[p][1];
        }
    }
    for (int i = tid; i < 32 * 48; i += 256) {
        int k = i / 48, po = i % 48;
        sww[k * 48 + po] = f2u(Wi1[(2 * po) * 32 + k], Wi1[(2 * po + 1) * 32 + k]);
    }
    __syncthreads();

    u64 tr[8], tz[8], tn[8];
#pragma unroll
    for (int p = 0; p < 8; p++) { tr[p] = 0ull; tz[p] = 0ull; tn[p] = 0ull; }
#pragma unroll 4
    for (int k = 0; k < 32; k++) {
        const u64* wrow = sww + k * 48;
        u64 wr = wrow[fy], wz = wrow[16 + fy], wn = wrow[32 + fy];
        const float4* xr = (const float4*)(sxx + k * XS + pbase);
        float4 a = xr[0], bq = xr[1];
        float xv[8] = {a.x, a.y, a.z, a.w, bq.x, bq.y, bq.z, bq.w};
#pragma unroll
        for (int p = 0; p < 8; p++) {
            u64 d = f2u(xv[p], xv[p]);
            tr[p] = ffma2(d, wr, tr[p]);
            tz[p] = ffma2(d, wz, tz[p]);
            tn[p] = ffma2(d, wn, tn[p]);
        }
    }
    float br0 = sb1[2 * fy],      br1 = sb1[2 * fy + 1];
    float bz0 = sb1[32 + 2 * fy], bz1 = sb1[32 + 2 * fy + 1];
    float bn0 = sb1[64 + 2 * fy], bn1 = sb1[64 + 2 * fy + 1];
#pragma unroll
    for (int p = 0; p < 8; p++) {
        int pp = pbase + p;
        if (pp < rcount) {
            u64* trow = (u64*)(g_table + (size_t)(s0 + pp) * 96);
            float2 a0 = u2f(tr[p]), a1 = u2f(tz[p]), a2 = u2f(tn[p]);
            trow[fy]      = f2u(a0.x + br0, a0.y + br1);
            trow[16 + fy] = f2u(a1.x + bz0, a1.y + bz1);
            trow[32 + fy] = f2u(a2.x + bn0, a2.y + bn1);
        }
    }
}

// ---------------- scan10: warp-autonomous, pairwise-prefetch epilogue ----------------
__global__ void __launch_bounds__(256, 2) scan10_kernel(const float* __restrict__ Wh,
                                                        const float* __restrict__ bh,
                                                        float* __restrict__ final_out)
{
    __shared__ __align__(16) u64   sww[32 * 48];
    __shared__ __align__(16) float shf[16 * SROW];
    __shared__ unsigned short sidx[STILE * L_N];
    __shared__ short slen[STILE];
    __shared__ float sbhn[32];

    int tid = threadIdx.x;
    int s0 = blockIdx.x * STILE;
    int pcount = min(STILE, P_N - s0);

    for (int i = tid; i < 32 * 48; i += 256) {
        int k = i / 48, po = i % 48;
        sww[k * 48 + po] = f2u(Wh[(2 * po) * 32 + k], Wh[(2 * po + 1) * 32 + k]);
    }
    if (tid < 32) sbhn[tid] = bh[64 + tid];
    if (tid < STILE) slen[tid] = (tid < pcount) ? (short)g_len[s0 + tid] : (short)-1;
    for (int i = tid; i < STILE * L_N; i += 256)
        sidx[i] = (i < pcount * L_N) ? (unsigned short)g_idx[(size_t)s0 * L_N + i] : (unsigned short)0;
    if (pcount < STILE) {
        for (int i = tid; i < 16 * SROW; i += 256) shf[i] = 0.0f;
        __syncthreads();
    }
    for (int i = tid; i < pcount * 8; i += 256) {
        int p = i >> 3, kq = i & 7;
        float4 v = ((const float4*)(g_p + (size_t)s0 * F_N))[i];
        float* r0 = &shf[(2 * kq) * SROW + 2 * p];
        r0[0] = v.x; r0[1] = v.y;
        float* r1 = &shf[(2 * kq + 1) * SROW + 2 * p];
        r1[0] = v.z; r1[1] = v.w;
    }
    __syncthreads();

    int px = tid >> 4;
    int fy = tid & 15;
    int pbase = px * 8;
    int wfirst = (tid >> 5) * 16;
    int tmax = slen[wfirst];

    for (int t = 0; t <= tmax; t++) {
        u64 ar[8], az[8], an[8];
#pragma unroll
        for (int p = 0; p < 8; p++) { ar[p] = 0ull; az[p] = 0ull; an[p] = 0ull; }

#pragma unroll 4
        for (int j = 0; j < 16; j++) {
            const u64* w0 = sww + (2 * j) * 48;
            const u64* w1 = sww + (2 * j + 1) * 48;
            u64 wr0 = w0[fy], wz0 = w0[16 + fy], wn0 = w0[32 + fy];
            u64 wr1 = w1[fy], wz1 = w1[16 + fy], wn1 = w1[32 + fy];
            const float4* hq = (const float4*)(shf + j * SROW + 2 * pbase);
            float4 q0 = hq[0], q1 = hq[1], q2 = hq[2], q3 = hq[3];
            float qe[8] = {q0.x, q0.z, q1.x, q1.z, q2.x, q2.z, q3.x, q3.z};
            float qo[8] = {q0.y, q0.w, q1.y, q1.w, q2.y, q2.w, q3.y, q3.w};
#pragma unroll
            for (int p = 0; p < 8; p++) {
                u64 he = f2u(qe[p], qe[p]);
                ar[p] = ffma2(he, wr0, ar[p]);
                az[p] = ffma2(he, wz0, az[p]);
                an[p] = ffma2(he, wn0, an[p]);
                u64 ho = f2u(qo[p], qo[p]);
                ar[p] = ffma2(ho, wr1, ar[p]);
                az[p] = ffma2(ho, wz1, az[p]);
                an[p] = ffma2(ho, wn1, an[p]);
            }
        }
        __syncwarp();

        {
            u64 ga0, ga1, ga2, gb0, gb1, gb2;
            {
                int cha = sidx[(pbase + 0) * L_N + t];
                const u64* tga = (const u64*)(g_table + (size_t)cha * 96);
                ga0 = ldg64(tga + fy); ga1 = ldg64(tga + 16 + fy); ga2 = ldg64(tga + 32 + fy);
                int chb = sidx[(pbase + 1) * L_N + t];
                const u64* tgb = (const u64*)(g_table + (size_t)chb * 96);
                gb0 = ldg64(tgb + fy); gb1 = ldg64(tgb + 16 + fy); gb2 = ldg64(tgb + 32 + fy);
            }
#pragma unroll
            for (int pr = 0; pr < 4; pr++) {
                u64 na0 = 0, na1 = 0, na2 = 0, nb0 = 0, nb1 = 0, nb2 = 0;
                if (pr < 3) {
                    int cha = sidx[(pbase + 2 * pr + 2) * L_N + t];
                    const u64* tga = (const u64*)(g_table + (size_t)cha * 96);
                    na0 = ldg64(tga + fy); na1 = ldg64(tga + 16 + fy); na2 = ldg64(tga + 32 + fy);
                    int chb = sidx[(pbase + 2 * pr + 3) * L_N + t];
                    const u64* tgb = (const u64*)(g_table + (size_t)chb * 96);
                    nb0 = ldg64(tgb + fy); nb1 = ldg64(tgb + 16 + fy); nb2 = ldg64(tgb + 32 + fy);
                }
#pragma unroll
                for (int s = 0; s < 2; s++) {
                    int pp = pbase + 2 * pr + s;
                    u64 cg0 = s ? gb0 : ga0;
                    u64 cg1 = s ? gb1 : ga1;
                    u64 cg2 = s ? gb2 : ga2;
                    int p = 2 * pr + s;
                    bool active = (t <= slen[pp]);
                    float2 gr = u2f(cg0), gz = u2f(cg1), gn = u2f(cg2);
                    float2 vr = u2f(ar[p]), vz = u2f(az[p]), vn = u2f(an[p]);
                    float2 hold = *(const float2*)(shf + fy * SROW + 2 * pp);
                    float h0, h1;
                    {
                        float r = fast_sigmoid(gr.x + vr.x);
                        float z = fast_sigmoid(gz.x + vz.x);
                        float n = fast_tanh(gn.x + r * (vn.x + sbhn[2 * fy]));
                        h0 = n + z * (hold.x - n);
                    }
                    {
                        float r = fast_sigmoid(gr.y + vr.y);
                        float z = fast_sigmoid(gz.y + vz.y);
                        float n = fast_tanh(gn.y + r * (vn.y + sbhn[2 * fy + 1]));
                        h1 = n + z * (hold.y - n);
                    }
                    if (active)
                        *(float2*)(shf + fy * SROW + 2 * pp) = make_float2(h0, h1);
                }
                ga0 = na0; ga1 = na1; ga2 = na2;
                gb0 = nb0; gb1 = nb1; gb2 = nb2;
            }
        }
        __syncwarp();
    }

    __syncthreads();

    int p = tid & (STILE - 1);
    int kc = tid >> 7;
    if (p < pcount) {
        float v[16];
#pragma unroll
        for (int j = 0; j < 16; j++) {
            int f = kc * 16 + j;
            v[j] = shf[(f >> 1) * SROW + 2 * p + (f & 1)];
        }
        float4* dst;
        if (final_out) {
            int ord = g_order[s0 + p];
            dst = (float4*)(final_out + (size_t)ord * F_N + kc * 16);
        } else {
            dst = (float4*)(g_p + (size_t)(s0 + p) * F_N + kc * 16);
        }
#pragma unroll
        for (int q = 0; q < 4; q++)
            dst[q] = make_float4(v[4 * q], v[4 * q + 1], v[4 * q + 2], v[4 * q + 3]);
        int ln = slen[p];
#pragma unroll 1
        for (int t = 0; t <= ln; t++) {
            int ch = sidx[p * L_N + t];
            float* base = g_agg + (size_t)ch * F_N + kc * 16;
            red_add_v4(base + 0,  make_float4(v[0],  v[1],  v[2],  v[3]));
            red_add_v4(base + 4,  make_float4(v[4],  v[5],  v[6],  v[7]));
            red_add_v4(base + 8,  make_float4(v[8],  v[9],  v[10], v[11]));
            red_add_v4(base + 12, make_float4(v[12], v[13], v[14], v[15]));
        }
    }
}

// ---------------- layer2g: 128 rows/block, fused gi2+gh2, gi1 table ----------------
__global__ void __launch_bounds__(256, 2) layer2g_kernel(float* __restrict__ c,
                                                         const float* __restrict__ Wi2,
                                                         const float* __restrict__ Wh2,
                                                         const float* __restrict__ bi2,
                                                         const float* __restrict__ bh2,
                                                         const float* __restrict__ Wi1,
                                                         const float* __restrict__ bi1,
                                                         const float* __restrict__ bh1,
                                                         int want_table)
{
    __shared__ __align__(16) u64   swa[32 * 48];
    __shared__ __align__(16) u64   swh[32 * 48];
    __shared__ __align__(16) float sagg[32 * XS];
    __shared__ __align__(16) float sc[32 * XS];
    __shared__ float sbi[96];
    __shared__ float sbhn2[32];
    __shared__ float sb1[96];

    int tid = threadIdx.x;
    int s0 = blockIdx.x * L2T;
    int rcount = min(L2T, C_N - s0);

    for (int i = tid; i < 32 * 48; i += 256) {
        int k = i / 48, po = i % 48;
        swa[k * 48 + po] = f2u(Wi2[(2 * po) * 32 + k], Wi2[(2 * po + 1) * 32 + k]);
        swh[k * 48 + po] = f2u(Wh2[(2 * po) * 32 + k], Wh2[(2 * po + 1) * 32 + k]);
    }
    if (tid < 96) {
        sbi[tid] = bi2[tid] + (tid < 64 ? bh2[tid] : 0.0f);
        sb1[tid] = bi1[tid] + (tid < 64 ? bh1[tid] : 0.0f);
    }
    if (tid < 32) sbhn2[tid] = bh2[64 + tid];
    if (rcount < L2T) {
        for (int i = tid; i < 32 * L2T; i += 256) {
            int p = i & (L2T - 1);
            if (p >= rcount) { sagg[(i >> 7) * XS + p] = 0.0f; sc[(i >> 7) * XS + p] = 0.0f; }
        }
    }
    for (int i = tid; i < rcount * 8; i += 256) {
        int p = i >> 3, kq = i & 7;
        float4 va = ((const float4*)(g_agg + (size_t)s0 * F_N))[i];
        sagg[(4 * kq + 0) * XS + p] = va.x;
        sagg[(4 * kq + 1) * XS + p] = va.y;
        sagg[(4 * kq + 2) * XS + p] = va.z;
        sagg[(4 * kq + 3) * XS + p] = va.w;
        ((float4*)(g_agg + (size_t)s0 * F_N))[i] = make_float4(0.f, 0.f, 0.f, 0.f);
        float4 vc = ((const float4*)(c + (size_t)s0 * F_N))[i];
        sc[(4 * kq + 0) * XS + p] = vc.x;
        sc[(4 * kq + 1) * XS + p] = vc.y;
        sc[(4 * kq + 2) * XS + p] = vc.z;
        sc[(4 * kq + 3) * XS + p] = vc.w;
    }
    __syncthreads();

    int px = tid >> 4, fy = tid & 15;
    int pbase = px * 8;

    u64 ir[8], iz[8], in_[8];
#pragma unroll
    for (int p = 0; p < 8; p++) { ir[p] = 0ull; iz[p] = 0ull; in_[p] = 0ull; }
#pragma unroll 4
    for (int k = 0; k < 32; k++) {
        const u64* wA = swa + k * 48;
        u64 war = wA[fy], waz = wA[16 + fy], wan = wA[32 + fy];
        const float4* xr = (const float4*)(sagg + k * XS + pbase);
        float4 a = xr[0], bq = xr[1];
        float av[8] = {a.x, a.y, a.z, a.w, bq.x, bq.y, bq.z, bq.w};
#pragma unroll
        for (int p = 0; p < 8; p++) {
            u64 da = f2u(av[p], av[p]);
            ir[p]  = ffma2(da, war, ir[p]);
            iz[p]  = ffma2(da, waz, iz[p]);
            in_[p] = ffma2(da, wan, in_[p]);
        }
    }

    u64 hr_[8], hz_[8], hn_[8];
#pragma unroll
    for (int p = 0; p < 8; p++) { hr_[p] = 0ull; hz_[p] = 0ull; hn_[p] = 0ull; }
#pragma unroll 4
    for (int k = 0; k < 32; k++) {
        const u64* wH = swh + k * 48;
        u64 whr = wH[fy], whz = wH[16 + fy], whn = wH[32 + fy];
        const float4* xr = (const float4*)(sc + k * XS + pbase);
        float4 a = xr[0], bq = xr[1];
        float cv[8] = {a.x, a.y, a.z, a.w, bq.x, bq.y, bq.z, bq.w};
#pragma unroll
        for (int p = 0; p < 8; p++) {
            u64 dc = f2u(cv[p], cv[p]);
            hr_[p] = ffma2(dc, whr, hr_[p]);
            hz_[p] = ffma2(dc, whz, hz_[p]);
            hn_[p] = ffma2(dc, whn, hn_[p]);
        }
    }

    float hn2[8][2];
#pragma unroll
    for (int p = 0; p < 8; p++) {
        int pp = pbase + p;
        if (pp < rcount) {
            int ch = s0 + pp;
            u64* cdst = (u64*)(c + (size_t)ch * F_N);
            float2 vi_r = u2f(ir[p]),  vi_z = u2f(iz[p]),  vi_n = u2f(in_[p]);
            float2 vh_r = u2f(hr_[p]), vh_z = u2f(hz_[p]), vh_n = u2f(hn_[p]);
#pragma unroll
            for (int half = 0; half < 2; half++) {
                int f = 2 * fy + half;
                float a_ir = half ? vi_r.y : vi_r.x;
                float a_iz = half ? vi_z.y : vi_z.x;
                float a_in = half ? vi_n.y : vi_n.x;
                float a_hr = half ? vh_r.y : vh_r.x;
                float a_hz = half ? vh_z.y : vh_z.x;
                float a_hn = half ? vh_n.y : vh_n.x;
                float r = fast_sigmoid(a_ir + sbi[f] + a_hr);
                float z = fast_sigmoid(a_iz + sbi[32 + f] + a_hz);
                float n = fast_tanh(a_in + sbi[64 + f] + r * (a_hn + sbhn2[f]));
                float hold = sc[f * XS + pp];
                hn2[p][half] = n + z * (hold - n);
            }
            cdst[fy] = f2u(hn2[p][0], hn2[p][1]);
        }
    }

    if (!want_table) return;
    __syncthreads();

#pragma unroll
    for (int p = 0; p < 8; p++) {
        int pp = pbase + p;
        if (pp < rcount) {
            sagg[(2 * fy) * XS + pp]     = hn2[p][0];
            sagg[(2 * fy + 1) * XS + pp] = hn2[p][1];
        }
    }
    for (int i = tid; i < 32 * 48; i += 256) {
        int k = i / 48, po = i % 48;
        swa[k * 48 + po] = f2u(Wi1[(2 * po) * 32 + k], Wi1[(2 * po + 1) * 32 + k]);
    }
    __syncthreads();

    u64 tr[8], tz[8], tn[8];
#pragma unroll
    for (int p = 0; p < 8; p++) { tr[p] = 0ull; tz[p] = 0ull; tn[p] = 0ull; }
#pragma unroll 4
    for (int k = 0; k < 32; k++) {
        const u64* wrow = swa + k * 48;
        u64 wr = wrow[fy], wz = wrow[16 + fy], wn = wrow[32 + fy];
        const float4* xr = (const float4*)(sagg + k * XS + pbase);
        float4 a = xr[0], bq = xr[1];
        float hv[8] = {a.x, a.y, a.z, a.w, bq.x, bq.y, bq.z, bq.w};
#pragma unroll
        for (int p = 0; p < 8; p++) {
            u64 hd = f2u(hv[p], hv[p]);
            tr[p] = ffma2(hd, wr, tr[p]);
            tz[p] = ffma2(hd, wz, tz[p]);
            tn[p] = ffma2(hd, wn, tn[p]);
        }
    }
    float br0 = sb1[2 * fy],      br1 = sb1[2 * fy + 1];
    float bz0 = sb1[32 + 2 * fy], bz1 = sb1[32 + 2 * fy + 1];
    float bn0 = sb1[64 + 2 * fy], bn1 = sb1[64 + 2 * fy + 1];
#pragma unroll
    for (int p = 0; p < 8; p++) {
        int pp = pbase + p;
        if (pp < rcount) {
            u64* trow = (u64*)(g_table + (size_t)(s0 + pp) * 96);
            float2 a0 = u2f(tr[p]), a1 = u2f(tz[p]), a2 = u2f(tn[p]);
            trow[fy]      = f2u(a0.x + br0, a0.y + br1);
            trow[16 + fy] = f2u(a1.x + bz0, a1.y + bz1);
            trow[32 + fy] = f2u(a2.x + bn0, a2.y + bn1);
        }
    }
}

// ---------------- launch ----------------
extern "C" void kernel_launch(void* const* d_in, const int* in_sizes, int n_in,
                              void* d_out, int out_size)
{
    const float* path_raw    = (const float*)d_in[0];
    const float* channel_raw = (const float*)d_in[1];
    const int*   pci         = (const int*)d_in[2];
    const int*   plen        = (const int*)d_in[3];
    // d_in[4] = num_steps (constant 5)
    const float* Wp  = (const float*)d_in[5];
    const float* bp  = (const float*)d_in[6];
    const float* Wc  = (const float*)d_in[7];
    const float* bc  = (const float*)d_in[8];
    const float* Wi1 = (const float*)d_in[9];
    const float* Wh1 = (const float*)d_in[10];
    const float* bi1 = (const float*)d_in[11];
    const float* bh1 = (const float*)d_in[12];
    const float* Wi2 = (const float*)d_in[13];
    const float* Wh2 = (const float*)d_in[14];
    const float* bi2 = (const float*)d_in[15];
    const float* bh2 = (const float*)d_in[16];

    float* outp = (float*)d_out;
    float* c    = outp + (size_t)P_N * F_N;

    int gridScan = (P_N + STILE - 1) / STILE;     // 1563

    hist_prefix_kernel<<<PB_BLOCKS, 256>>>(plen);
    scatter_kernel<<<PB_BLOCKS, 256>>>(plen);
    buildinit_gi_kernel<<<PB2 + CB2, 256>>>(plen, pci, path_raw, channel_raw,
                                            Wp, bp, Wc, bc, Wi1, bi1, bh1, c);
    for (int st = 0; st < NSTEPS; st++) {
        scan10_kernel<<<gridScan, 256>>>(Wh1, bh1, (st == NSTEPS - 1) ? outp : nullptr);
        layer2g_kernel<<<L2B, 256>>>(c, Wi2, Wh2, bi2, bh2, Wi1, bi1, bh1,
                                     (st < NSTEPS - 1) ? 1 : 0);
    }
}

// round 16
// speedup vs baseline: 1.0717x; 1.0091x over previous
#include <cuda_runtime.h>

#define P_N 200000
#define C_N 50000
#define L_N 8
#define F_N 32
#define DIN 64
#define NSTEPS 5

#define PB_BLOCKS ((P_N + 255) / 256)   // histogram blocks (782)
#define BI_TILE 128
#define PB2 ((P_N + BI_TILE - 1) / BI_TILE)   // 1563
#define CB2 ((C_N + BI_TILE - 1) / BI_TILE)   // 391

#define STILE 128                       // scan paths per block
#define SROW 260                        // floats per h-pair row
#define L2T 128                         // layer2 rows per block
#define L2B ((C_N + L2T - 1) / L2T)     // 391
#define XS 132                          // float stride for staging

typedef unsigned long long u64;

// ---------------- device scratch ----------------
__device__ float g_p[(size_t)P_N * F_N];
__device__ int   g_order[P_N];
__device__ int   g_idx[(size_t)P_N * L_N];
__device__ int   g_len[P_N];
__device__ float g_agg[(size_t)C_N * F_N];
__device__ float g_table[(size_t)C_N * 96];
__device__ int   g_blkhist[PB_BLOCKS * 8];
__device__ int   g_blkoff[PB_BLOCKS * 8];
__device__ int   g_done;

// ---------------- helpers ----------------
__device__ __forceinline__ u64 ffma2(u64 a, u64 b, u64 c) {
    u64 d;
    asm("fma.rn.f32x2 %0, %1, %2, %3;" : "=l"(d) : "l"(a), "l"(b), "l"(c));
    return d;
}
__device__ __forceinline__ float2 u2f(u64 v) {
    float2 r;
    asm("mov.b64 {%0,%1}, %2;" : "=f"(r.x), "=f"(r.y) : "l"(v));
    return r;
}
__device__ __forceinline__ u64 f2u(float a, float b) {
    u64 r;
    asm("mov.b64 %0, {%1,%2};" : "=l"(r) : "f"(a), "f"(b));
    return r;
}

__device__ __forceinline__ float tanh_ap(float x) {
    float y;
    asm("tanh.approx.f32 %0, %1;" : "=f"(y) : "f"(x));
    return y;
}
__device__ __forceinline__ float fast_sigmoid(float v) {
    return fmaf(0.5f, tanh_ap(0.5f * v), 0.5f);
}
__device__ __forceinline__ float fast_tanh(float v) { return tanh_ap(v); }

__device__ __forceinline__ void red_add_v4(float* p, float4 v) {
    asm volatile("red.global.add.v4.f32 [%0], {%1,%2,%3,%4};"
                 :: "l"(p), "f"(v.x), "f"(v.y), "f"(v.z), "f"(v.w) : "memory");
}
__device__ __forceinline__ u64 ldg64(const u64* p) {
    u64 v;
    asm("ld.global.nc.b64 %0, [%1];" : "=l"(v) : "l"(p));
    return v;
}

// ---------------- hist + per-block offsets (last-block-done) ----------------
__global__ void __launch_bounds__(256) hist_prefix_kernel(const int* __restrict__ plen) {
    __shared__ int lh[8];
    __shared__ int slast;
    int tid = threadIdx.x;
    if (tid < 8) lh[tid] = 0;
    __syncthreads();
    int i = blockIdx.x * 256 + tid;
    if (i < P_N) {
        int b = plen[i]; b = b < 0 ? 0 : (b > 7 ? 7 : b);
        atomicAdd(&lh[b], 1);
    }
    __syncthreads();
    if (tid < 8) g_blkhist[blockIdx.x * 8 + tid] = lh[tid];
    __threadfence();
    if (tid == 0) {
        int t = atomicAdd(&g_done, 1);
        slast = (t == gridDim.x - 1) ? 1 : 0;
    }
    __syncthreads();
    if (slast) {
        __threadfence();
        int local[8] = {0, 0, 0, 0, 0, 0, 0, 0};
        for (int j = tid; j < PB_BLOCKS; j += 256) {
#pragma unroll
            for (int b = 0; b < 8; b++) local[b] += g_blkhist[j * 8 + b];
        }
        if (tid < 8) lh[tid] = 0;
        __syncthreads();
#pragma unroll
        for (int b = 0; b < 8; b++) atomicAdd(&lh[b], local[b]);
        __syncthreads();
        __shared__ int base[8];
        if (tid == 0) {
            int acc = 0;
#pragma unroll
            for (int b = 7; b >= 0; b--) { int cv = lh[b]; base[b] = acc; acc += cv; }
            g_done = 0;
        }
        __syncthreads();
        if (tid < 8) {
            int b = tid;
            int acc = base[b];
            for (int j = 0; j < PB_BLOCKS; j++) {
                g_blkoff[j * 8 + b] = acc;
                acc += g_blkhist[j * 8 + b];
            }
        }
    }
}

__global__ void __launch_bounds__(256) scatter_kernel(const int* __restrict__ plen) {
    __shared__ int loff[8];
    int tid = threadIdx.x;
    if (tid < 8) loff[tid] = g_blkoff[blockIdx.x * 8 + tid];
    __syncthreads();
    int i = blockIdx.x * 256 + tid;
    if (i < P_N) {
        int b = plen[i]; b = b < 0 ? 0 : (b > 7 ? 7 : b);
        int pos = atomicAdd(&loff[b], 1);
        g_order[pos] = i;
    }
}

// ---------------- build paths: init p (sorted order), gather len/idx ----------------
__global__ void __launch_bounds__(256, 2) build_paths_kernel(const int* __restrict__ plen,
                                                             const int* __restrict__ pci,
                                                             const float* __restrict__ praw,
                                                             const float* __restrict__ Wp,
                                                             const float* __restrict__ bp)
{
    __shared__ __align__(16) float sxx[64 * XS];
    __shared__ __align__(16) u64   sww[64 * 16];
    __shared__ int   sord[BI_TILE];
    __shared__ float sb[32];

    int tid = threadIdx.x;
    int s0 = blockIdx.x * BI_TILE;
    int rcount = min(BI_TILE, P_N - s0);

    for (int i = tid; i < 64 * 16; i += 256) {
        int d = i >> 4, o = i & 15;
        float2 w = ((const float2*)(Wp + d * 32))[o];
        sww[d * 16 + o] = f2u(w.x, w.y);
    }
    if (tid < 32) sb[tid] = bp[tid];
    if (tid < BI_TILE) {
        int row = s0 + tid;
        if (row < P_N) {
            int sr = g_order[row];
            sord[tid] = sr;
            g_len[row] = plen[sr];
            const int4* si = (const int4*)(pci + (size_t)sr * L_N);
            int4* di = (int4*)(g_idx + (size_t)row * L_N);
            di[0] = si[0]; di[1] = si[1];
        }
    }
    __syncthreads();

    for (int i = tid; i < rcount * 16; i += 256) {
        int r = i >> 4, q = i & 15;
        float4 v = ((const float4*)(praw + (size_t)sord[r] * DIN))[q];
        sxx[(4 * q + 0) * XS + r] = v.x;
        sxx[(4 * q + 1) * XS + r] = v.y;
        sxx[(4 * q + 2) * XS + r] = v.z;
        sxx[(4 * q + 3) * XS + r] = v.w;
    }
    __syncthreads();

    int px = tid >> 4, fy = tid & 15;
    int pbase = px * 8;
    u64 acc[8];
#pragma unroll
    for (int p = 0; p < 8; p++) acc[p] = 0ull;
#pragma unroll 4
    for (int k = 0; k < 64; k++) {
        u64 w = sww[k * 16 + fy];
        const float4* xr = (const float4*)(sxx + k * XS + pbase);
        float4 a = xr[0], bq = xr[1];
        float xv[8] = {a.x, a.y, a.z, a.w, bq.x, bq.y, bq.z, bq.w};
#pragma unroll
        for (int p = 0; p < 8; p++)
            acc[p] = ffma2(f2u(xv[p], xv[p]), w, acc[p]);
    }
    float b0 = sb[2 * fy], b1 = sb[2 * fy + 1];
#pragma unroll
    for (int p = 0; p < 8; p++) {
        int pp = pbase + p;
        if (pp < rcount) {
            float2 v = u2f(acc[p]);
            ((u64*)(g_p + (size_t)(s0 + pp) * F_N))[fy] =
                f2u(fmaxf(v.x + b0, 0.0f), fmaxf(v.y + b1, 0.0f));
        }
    }
}

// ---------------- build channels: init c + zero agg + step0 gi1 table ----------------
__global__ void __launch_bounds__(256, 2) build_chan_kernel(const float* __restrict__ craw,
                                                            const float* __restrict__ Wc,
                                                            const float* __restrict__ bc,
                                                            const float* __restrict__ Wi1,
                                                            const float* __restrict__ bi1,
                                                            const float* __restrict__ bh1,
                                                            float* __restrict__ c)
{
    __shared__ __align__(16) float sxx[64 * XS];
    __shared__ __align__(16) u64   sww[32 * 48];
    __shared__ float sb[32];
    __shared__ float sb1[96];

    int tid = threadIdx.x;
    int s0 = blockIdx.x * BI_TILE;
    int rcount = min(BI_TILE, C_N - s0);

    for (int i = tid; i < 64 * 16; i += 256) {
        int d = i >> 4, o = i & 15;
        float2 w = ((const float2*)(Wc + d * 32))[o];
        sww[d * 16 + o] = f2u(w.x, w.y);
    }
    if (tid < 32) sb[tid] = bc[tid];
    if (tid < 96) sb1[tid] = bi1[tid] + (tid < 64 ? bh1[tid] : 0.0f);
    __syncthreads();

    for (int i = tid; i < rcount * 16; i += 256) {
        int r = i >> 4, q = i & 15;
        float4 v = ((const float4*)(craw + (size_t)(s0 + r) * DIN))[q];
        sxx[(4 * q + 0) * XS + r] = v.x;
        sxx[(4 * q + 1) * XS + r] = v.y;
        sxx[(4 * q + 2) * XS + r] = v.z;
        sxx[(4 * q + 3) * XS + r] = v.w;
    }
    __syncthreads();

    int px = tid >> 4, fy = tid & 15;
    int pbase = px * 8;
    u64 acc[8];
#pragma unroll
    for (int p = 0; p < 8; p++) acc[p] = 0ull;
#pragma unroll 4
    for (int k = 0; k < 64; k++) {
        u64 w = sww[k * 16 + fy];
        const float4* xr = (const float4*)(sxx + k * XS + pbase);
        float4 a = xr[0], bq = xr[1];
        float xv[8] = {a.x, a.y, a.z, a.w, bq.x, bq.y, bq.z, bq.w};
#pragma unroll
        for (int p = 0; p < 8; p++)
            acc[p] = ffma2(f2u(xv[p], xv[p]), w, acc[p]);
    }
    float cres[8][2];
    float b0 = sb[2 * fy], b1 = sb[2 * fy + 1];
#pragma unroll
    for (int p = 0; p < 8; p++) {
        int pp = pbase + p;
        float2 v = u2f(acc[p]);
        float r0 = fmaxf(v.x + b0, 0.0f);
        float r1 = fmaxf(v.y + b1, 0.0f);
        cres[p][0] = r0; cres[p][1] = r1;
        if (pp < rcount)
            ((u64*)(c + (size_t)(s0 + pp) * F_N))[fy] = f2u(r0, r1);
    }

    __syncthreads();
    for (int i = tid; i < rcount * 8; i += 256)
        ((float4*)(g_agg + (size_t)s0 * F_N))[i] = make_float4(0.f, 0.f, 0.f, 0.f);
#pragma unroll
    for (int p = 0; p < 8; p++) {
        int pp = pbase + p;
        if (pp < rcount) {
            sxx[(2 * fy) * XS + pp]     = cres[p][0];
            sxx[(2 * fy + 1) * XS + pp] = cres[p][1];
        }
    }
    for (int i = tid; i < 32 * 48; i += 256) {
        int k = i / 48, po = i % 48;
        sww[k * 48 + po] = f2u(Wi1[(2 * po) * 32 + k], Wi1[(2 * po + 1) * 32 + k]);
    }
    __syncthreads();

    u64 tr[8], tz[8], tn[8];
#pragma unroll
    for (int p = 0; p < 8; p++) { tr[p] = 0ull; tz[p] = 0ull; tn[p] = 0ull; }
#pragma unroll 4
    for (int k = 0; k < 32; k++) {
        const u64* wrow = sww + k * 48;
        u64 wr = wrow[fy], wz = wrow[16 + fy], wn = wrow[32 + fy];
        const float4* xr = (const float4*)(sxx + k * XS + pbase);
        float4 a = xr[0], bq = xr[1];
        float xv[8] = {a.x, a.y, a.z, a.w, bq.x, bq.y, bq.z, bq.w};
#pragma unroll
        for (int p = 0; p < 8; p++) {
            u64 d = f2u(xv[p], xv[p]);
            tr[p] = ffma2(d, wr, tr[p]);
            tz[p] = ffma2(d, wz, tz[p]);
            tn[p] = ffma2(d, wn, tn[p]);
        }
    }
    float br0 = sb1[2 * fy],      br1 = sb1[2 * fy + 1];
    float bz0 = sb1[32 + 2 * fy], bz1 = sb1[32 + 2 * fy + 1];
    float bn0 = sb1[64 + 2 * fy], bn1 = sb1[64 + 2 * fy + 1];
#pragma unroll
    for (int p = 0; p < 8; p++) {
        int pp = pbase + p;
        if (pp < rcount) {
            u64* trow = (u64*)(g_table + (size_t)(s0 + pp) * 96);
            float2 a0 = u2f(tr[p]), a1 = u2f(tz[p]), a2 = u2f(tn[p]);
            trow[fy]      = f2u(a0.x + br0, a0.y + br1);
            trow[16 + fy] = f2u(a1.x + bz0, a1.y + bz1);
            trow[32 + fy] = f2u(a2.x + bn0, a2.y + bn1);
        }
    }
}

// ---------------- scan10: warp-autonomous, pairwise-prefetch epilogue ----------------
__global__ void __launch_bounds__(256, 2) scan10_kernel(const float* __restrict__ Wh,
                                                        const float* __restrict__ bh,
                                                        float* __restrict__ final_out)
{
    __shared__ __align__(16) u64   sww[32 * 48];
    __shared__ __align__(16) float shf[16 * SROW];
    __shared__ unsigned short sidx[STILE * L_N];
    __shared__ short slen[STILE];
    __shared__ float sbhn[32];

    int tid = threadIdx.x;
    int s0 = blockIdx.x * STILE;
    int pcount = min(STILE, P_N - s0);

    for (int i = tid; i < 32 * 48; i += 256) {
        int k = i / 48, po = i % 48;
        sww[k * 48 + po] = f2u(Wh[(2 * po) * 32 + k], Wh[(2 * po + 1) * 32 + k]);
    }
    if (tid < 32) sbhn[tid] = bh[64 + tid];
    if (tid < STILE) slen[tid] = (tid < pcount) ? (short)g_len[s0 + tid] : (short)-1;
    for (int i = tid; i < STILE * L_N; i += 256)
        sidx[i] = (i < pcount * L_N) ? (unsigned short)g_idx[(size_t)s0 * L_N + i] : (unsigned short)0;
    if (pcount < STILE) {
        for (int i = tid; i < 16 * SROW; i += 256) shf[i] = 0.0f;
        __syncthreads();
    }
    for (int i = tid; i < pcount * 8; i += 256) {
        int p = i >> 3, kq = i & 7;
        float4 v = ((const float4*)(g_p + (size_t)s0 * F_N))[i];
        float* r0 = &shf[(2 * kq) * SROW + 2 * p];
        r0[0] = v.x; r0[1] = v.y;
        float* r1 = &shf[(2 * kq + 1) * SROW + 2 * p];
        r1[0] = v.z; r1[1] = v.w;
    }
    __syncthreads();

    int px = tid >> 4;
    int fy = tid & 15;
    int pbase = px * 8;
    int wfirst = (tid >> 5) * 16;
    int tmax = slen[wfirst];

    for (int t = 0; t <= tmax; t++) {
        u64 ar[8], az[8], an[8];
#pragma unroll
        for (int p = 0; p < 8; p++) { ar[p] = 0ull; az[p] = 0ull; an[p] = 0ull; }

#pragma unroll 4
        for (int j = 0; j < 16; j++) {
            const u64* w0 = sww + (2 * j) * 48;
            const u64* w1 = sww + (2 * j + 1) * 48;
            u64 wr0 = w0[fy], wz0 = w0[16 + fy], wn0 = w0[32 + fy];
            u64 wr1 = w1[fy], wz1 = w1[16 + fy], wn1 = w1[32 + fy];
            const float4* hq = (const float4*)(shf + j * SROW + 2 * pbase);
            float4 q0 = hq[0], q1 = hq[1], q2 = hq[2], q3 = hq[3];
            float qe[8] = {q0.x, q0.z, q1.x, q1.z, q2.x, q2.z, q3.x, q3.z};
            float qo[8] = {q0.y, q0.w, q1.y, q1.w, q2.y, q2.w, q3.y, q3.w};
#pragma unroll
            for (int p = 0; p < 8; p++) {
                u64 he = f2u(qe[p], qe[p]);
                ar[p] = ffma2(he, wr0, ar[p]);
                az[p] = ffma2(he, wz0, az[p]);
                an[p] = ffma2(he, wn0, an[p]);
                u64 ho = f2u(qo[p], qo[p]);
                ar[p] = ffma2(ho, wr1, ar[p]);
                az[p] = ffma2(ho, wz1, az[p]);
                an[p] = ffma2(ho, wn1, an[p]);
            }
        }
        __syncwarp();

        {
            u64 ga0, ga1, ga2, gb0, gb1, gb2;
            {
                int cha = sidx[(pbase + 0) * L_N + t];
                const u64* tga = (const u64*)(g_table + (size_t)cha * 96);
                ga0 = ldg64(tga + fy); ga1 = ldg64(tga + 16 + fy); ga2 = ldg64(tga + 32 + fy);
                int chb = sidx[(pbase + 1) * L_N + t];
                const u64* tgb = (const u64*)(g_table + (size_t)chb * 96);
                gb0 = ldg64(tgb + fy); gb1 = ldg64(tgb + 16 + fy); gb2 = ldg64(tgb + 32 + fy);
            }
#pragma unroll
            for (int pr = 0; pr < 4; pr++) {
                u64 na0 = 0, na1 = 0, na2 = 0, nb0 = 0, nb1 = 0, nb2 = 0;
                if (pr < 3) {
                    int cha = sidx[(pbase + 2 * pr + 2) * L_N + t];
                    const u64* tga = (const u64*)(g_table + (size_t)cha * 96);
                    na0 = ldg64(tga + fy); na1 = ldg64(tga + 16 + fy); na2 = ldg64(tga + 32 + fy);
                    int chb = sidx[(pbase + 2 * pr + 3) * L_N + t];
                    const u64* tgb = (const u64*)(g_table + (size_t)chb * 96);
                    nb0 = ldg64(tgb + fy); nb1 = ldg64(tgb + 16 + fy); nb2 = ldg64(tgb + 32 + fy);
                }
#pragma unroll
                for (int s = 0; s < 2; s++) {
                    int pp = pbase + 2 * pr + s;
                    u64 cg0 = s ? gb0 : ga0;
                    u64 cg1 = s ? gb1 : ga1;
                    u64 cg2 = s ? gb2 : ga2;
                    int p = 2 * pr + s;
                    bool active = (t <= slen[pp]);
                    float2 gr = u2f(cg0), gz = u2f(cg1), gn = u2f(cg2);
                    float2 vr = u2f(ar[p]), vz = u2f(az[p]), vn = u2f(an[p]);
                    float2 hold = *(const float2*)(shf + fy * SROW + 2 * pp);
                    float h0, h1;
                    {
                        float r = fast_sigmoid(gr.x + vr.x);
                        float z = fast_sigmoid(gz.x + vz.x);
                        float n = fast_tanh(gn.x + r * (vn.x + sbhn[2 * fy]));
                        h0 = n + z * (hold.x - n);
                    }
                    {
                        float r = fast_sigmoid(gr.y + vr.y);
                        float z = fast_sigmoid(gz.y + vz.y);
                        float n = fast_tanh(gn.y + r * (vn.y + sbhn[2 * fy + 1]));
                        h1 = n + z * (hold.y - n);
                    }
                    if (active)
                        *(float2*)(shf + fy * SROW + 2 * pp) = make_float2(h0, h1);
                }
                ga0 = na0; ga1 = na1; ga2 = na2;
                gb0 = nb0; gb1 = nb1; gb2 = nb2;
            }
        }
        __syncwarp();
    }

    __syncthreads();

    int p = tid & (STILE - 1);
    int kc = tid >> 7;
    if (p < pcount) {
        float v[16];
#pragma unroll
        for (int j = 0; j < 16; j++) {
            int f = kc * 16 + j;
            v[j] = shf[(f >> 1) * SROW + 2 * p + (f & 1)];
        }
        float4* dst;
        if (final_out) {
            int ord = g_order[s0 + p];
            dst = (float4*)(final_out + (size_t)ord * F_N + kc * 16);
        } else {
            dst = (float4*)(g_p + (size_t)(s0 + p) * F_N + kc * 16);
        }
#pragma unroll
        for (int q = 0; q < 4; q++)
            dst[q] = make_float4(v[4 * q], v[4 * q + 1], v[4 * q + 2], v[4 * q + 3]);
        int ln = slen[p];
#pragma unroll 1
        for (int t = 0; t <= ln; t++) {
            int ch = sidx[p * L_N + t];
            float* base = g_agg + (size_t)ch * F_N + kc * 16;
            red_add_v4(base + 0,  make_float4(v[0],  v[1],  v[2],  v[3]));
            red_add_v4(base + 4,  make_float4(v[4],  v[5],  v[6],  v[7]));
            red_add_v4(base + 8,  make_float4(v[8],  v[9],  v[10], v[11]));
            red_add_v4(base + 12, make_float4(v[12], v[13], v[14], v[15]));
        }
    }
}

// ---------------- layer2g: 128 rows/block, fused gi2+gh2, gi1 table ----------------
__global__ void __launch_bounds__(256, 2) layer2g_kernel(float* __restrict__ c,
                                                         const float* __restrict__ Wi2,
                                                         const float* __restrict__ Wh2,
                                                         const float* __restrict__ bi2,
                                                         const float* __restrict__ bh2,
                                                         const float* __restrict__ Wi1,
                                                         const float* __restrict__ bi1,
                                                         const float* __restrict__ bh1,
                                                         int want_table)
{
    __shared__ __align__(16) u64   swa[32 * 48];
    __shared__ __align__(16) u64   swh[32 * 48];
    __shared__ __align__(16) float sagg[32 * XS];
    __shared__ __align__(16) float sc[32 * XS];
    __shared__ float sbi[96];
    __shared__ float sbhn2[32];
    __shared__ float sb1[96];

    int tid = threadIdx.x;
    int s0 = blockIdx.x * L2T;
    int rcount = min(L2T, C_N - s0);

    for (int i = tid; i < 32 * 48; i += 256) {
        int k = i / 48, po = i % 48;
        swa[k * 48 + po] = f2u(Wi2[(2 * po) * 32 + k], Wi2[(2 * po + 1) * 32 + k]);
        swh[k * 48 + po] = f2u(Wh2[(2 * po) * 32 + k], Wh2[(2 * po + 1) * 32 + k]);
    }
    if (tid < 96) {
        sbi[tid] = bi2[tid] + (tid < 64 ? bh2[tid] : 0.0f);
        sb1[tid] = bi1[tid] + (tid < 64 ? bh1[tid] : 0.0f);
    }
    if (tid < 32) sbhn2[tid] = bh2[64 + tid];
    if (rcount < L2T) {
        for (int i = tid; i < 32 * L2T; i += 256) {
            int p = i & (L2T - 1);
            if (p >= rcount) { sagg[(i >> 7) * XS + p] = 0.0f; sc[(i >> 7) * XS + p] = 0.0f; }
        }
    }
    for (int i = tid; i < rcount * 8; i += 256) {
        int p = i >> 3, kq = i & 7;
        float4 va = ((const float4*)(g_agg + (size_t)s0 * F_N))[i];
        sagg[(4 * kq + 0) * XS + p] = va.x;
        sagg[(4 * kq + 1) * XS + p] = va.y;
        sagg[(4 * kq + 2) * XS + p] = va.z;
        sagg[(4 * kq + 3) * XS + p] = va.w;
        ((float4*)(g_agg + (size_t)s0 * F_N))[i] = make_float4(0.f, 0.f, 0.f, 0.f);
        float4 vc = ((const float4*)(c + (size_t)s0 * F_N))[i];
        sc[(4 * kq + 0) * XS + p] = vc.x;
        sc[(4 * kq + 1) * XS + p] = vc.y;
        sc[(4 * kq + 2) * XS + p] = vc.z;
        sc[(4 * kq + 3) * XS + p] = vc.w;
    }
    __syncthreads();

    int px = tid >> 4, fy = tid & 15;
    int pbase = px * 8;

    // early-issue Wi1 restage loads (consumed after the barrier below)
    u64 wi1regs[6];
    if (want_table) {
#pragma unroll
        for (int r = 0; r < 6; r++) {
            int i = tid + r * 256;
            int k = i / 48, po = i % 48;
            wi1regs[r] = f2u(__ldg(Wi1 + (2 * po) * 32 + k), __ldg(Wi1 + (2 * po + 1) * 32 + k));
        }
    }

    u64 ir[8], iz[8], in_[8];
#pragma unroll
    for (int p = 0; p < 8; p++) { ir[p] = 0ull; iz[p] = 0ull; in_[p] = 0ull; }
#pragma unroll 4
    for (int k = 0; k < 32; k++) {
        const u64* wA = swa + k * 48;
        u64 war = wA[fy], waz = wA[16 + fy], wan = wA[32 + fy];
        const float4* xr = (const float4*)(sagg + k * XS + pbase);
        float4 a = xr[0], bq = xr[1];
        float av[8] = {a.x, a.y, a.z, a.w, bq.x, bq.y, bq.z, bq.w};
#pragma unroll
        for (int p = 0; p < 8; p++) {
            u64 da = f2u(av[p], av[p]);
            ir[p]  = ffma2(da, war, ir[p]);
            iz[p]  = ffma2(da, waz, iz[p]);
            in_[p] = ffma2(da, wan, in_[p]);
        }
    }

    u64 hr_[8], hz_[8], hn_[8];
#pragma unroll
    for (int p = 0; p < 8; p++) { hr_[p] = 0ull; hz_[p] = 0ull; hn_[p] = 0ull; }
#pragma unroll 4
    for (int k = 0; k < 32; k++) {
        const u64* wH = swh + k * 48;
        u64 whr = wH[fy], whz = wH[16 + fy], whn = wH[32 + fy];
        const float4* xr = (const float4*)(sc + k * XS + pbase);
        float4 a = xr[0], bq = xr[1];
        float cv[8] = {a.x, a.y, a.z, a.w, bq.x, bq.y, bq.z, bq.w};
#pragma unroll
        for (int p = 0; p < 8; p++) {
            u64 dc = f2u(cv[p], cv[p]);
            hr_[p] = ffma2(dc, whr, hr_[p]);
            hz_[p] = ffma2(dc, whz, hz_[p]);
            hn_[p] = ffma2(dc, whn, hn_[p]);
        }
    }

    float hn2[8][2];
#pragma unroll
    for (int p = 0; p < 8; p++) {
        int pp = pbase + p;
        if (pp < rcount) {
            int ch = s0 + pp;
            u64* cdst = (u64*)(c + (size_t)ch * F_N);
            float2 vi_r = u2f(ir[p]),  vi_z = u2f(iz[p]),  vi_n = u2f(in_[p]);
            float2 vh_r = u2f(hr_[p]), vh_z = u2f(hz_[p]), vh_n = u2f(hn_[p]);
#pragma unroll
            for (int half = 0; half < 2; half++) {
                int f = 2 * fy + half;
                float a_ir = half ? vi_r.y : vi_r.x;
                float a_iz = half ? vi_z.y : vi_z.x;
                float a_in = half ? vi_n.y : vi_n.x;
                float a_hr = half ? vh_r.y : vh_r.x;
                float a_hz = half ? vh_z.y : vh_z.x;
                float a_hn = half ? vh_n.y : vh_n.x;
                float r = fast_sigmoid(a_ir + sbi[f] + a_hr);
                float z = fast_sigmoid(a_iz + sbi[32 + f] + a_hz);
                float n = fast_tanh(a_in + sbi[64 + f] + r * (a_hn + sbhn2[f]));
                float hold = sc[f * XS + pp];
                hn2[p][half] = n + z * (hold - n);
            }
            cdst[fy] = f2u(hn2[p][0], hn2[p][1]);
        }
    }

    if (!want_table) return;
    __syncthreads();

#pragma unroll
    for (int p = 0; p < 8; p++) {
        int pp = pbase + p;
        if (pp < rcount) {
            sagg[(2 * fy) * XS + pp]     = hn2[p][0];
            sagg[(2 * fy + 1) * XS + pp] = hn2[p][1];
        }
    }
#pragma unroll
    for (int r = 0; r < 6; r++) {
        int i = threadIdx.x + r * 256;
        int k = i / 48, po = i % 48;
        swa[k * 48 + po] = wi1regs[r];
    }
    __syncthreads();

    u64 tr[8], tz[8], tn[8];
#pragma unroll
    for (int p = 0; p < 8; p++) { tr[p] = 0ull; tz[p] = 0ull; tn[p] = 0ull; }
#pragma unroll 4
    for (int k = 0; k < 32; k++) {
        const u64* wrow = swa + k * 48;
        u64 wr = wrow[fy], wz = wrow[16 + fy], wn = wrow[32 + fy];
        const float4* xr = (const float4*)(sagg + k * XS + pbase);
        float4 a = xr[0], bq = xr[1];
        float hv[8] = {a.x, a.y, a.z, a.w, bq.x, bq.y, bq.z, bq.w};
#pragma unroll
        for (int p = 0; p < 8; p++) {
            u64 hd = f2u(hv[p], hv[p]);
            tr[p] = ffma2(hd, wr, tr[p]);
            tz[p] = ffma2(hd, wz, tz[p]);
            tn[p] = ffma2(hd, wn, tn[p]);
        }
    }
    float br0 = sb1[2 * fy],      br1 = sb1[2 * fy + 1];
    float bz0 = sb1[32 + 2 * fy], bz1 = sb1[32 + 2 * fy + 1];
    float bn0 = sb1[64 + 2 * fy], bn1 = sb1[64 + 2 * fy + 1];
#pragma unroll
    for (int p = 0; p < 8; p++) {
        int pp = pbase + p;
        if (pp < rcount) {
            u64* trow = (u64*)(g_table + (size_t)(s0 + pp) * 96);
            float2 a0 = u2f(tr[p]), a1 = u2f(tz[p]), a2 = u2f(tn[p]);
            trow[fy]      = f2u(a0.x + br0, a0.y + br1);
            trow[16 + fy] = f2u(a1.x + bz0, a1.y + bz1);
            trow[32 + fy] = f2u(a2.x + bn0, a2.y + bn1);
        }
    }
}

// ---------------- launch ----------------
extern "C" void kernel_launch(void* const* d_in, const int* in_sizes, int n_in,
                              void* d_out, int out_size)
{
    const float* path_raw    = (const float*)d_in[0];
    const float* channel_raw = (const float*)d_in[1];
    const int*   pci         = (const int*)d_in[2];
    const int*   plen        = (const int*)d_in[3];
    // d_in[4] = num_steps (constant 5)
    const float* Wp  = (const float*)d_in[5];
    const float* bp  = (const float*)d_in[6];
    const float* Wc  = (const float*)d_in[7];
    const float* bc  = (const float*)d_in[8];
    const float* Wi1 = (const float*)d_in[9];
    const float* Wh1 = (const float*)d_in[10];
    const float* bi1 = (const float*)d_in[11];
    const float* bh1 = (const float*)d_in[12];
    const float* Wi2 = (const float*)d_in[13];
    const float* Wh2 = (const float*)d_in[14];
    const float* bi2 = (const float*)d_in[15];
    const float* bh2 = (const float*)d_in[16];

    float* outp = (float*)d_out;
    float* c    = outp + (size_t)P_N * F_N;

    int gridScan = (P_N + STILE - 1) / STILE;     // 1563

    hist_prefix_kernel<<<PB_BLOCKS, 256>>>(plen);                       // 1
    scatter_kernel<<<PB_BLOCKS, 256>>>(plen);                           // 2
    build_paths_kernel<<<PB2, 256>>>(plen, pci, path_raw, Wp, bp);      // 3
    build_chan_kernel<<<CB2, 256>>>(channel_raw, Wc, bc, Wi1, bi1, bh1, c);  // 4
    for (int st = 0; st < NSTEPS; st++) {
        scan10_kernel<<<gridScan, 256>>>(Wh1, bh1, (st == NSTEPS - 1) ? outp : nullptr);  // 5
        layer2g_kernel<<<L2B, 256>>>(c, Wi2, Wh2, bi2, bh2, Wi1, bi1, bh1,
                                     (st < NSTEPS - 1) ? 1 : 0);        // 6 <- profiled
    }
}

// round 17
// speedup vs baseline: 1.1127x; 1.0382x over previous
#include <cuda_runtime.h>

#define P_N 200000
#define C_N 50000
#define L_N 8
#define F_N 32
#define DIN 64
#define NSTEPS 5

#define PB_BLOCKS ((P_N + 255) / 256)
#define BI_TILE 128
#define PB2 ((P_N + BI_TILE - 1) / BI_TILE)
#define CB2 ((C_N + BI_TILE - 1) / BI_TILE)

#define STILE 128
#define SROW 260
#define L2T 128
#define L2B ((C_N + L2T - 1) / L2T)
#define XS 132

typedef unsigned long long u64;

// ---------------- device scratch ----------------
__device__ float g_p[(size_t)P_N * F_N];
__device__ int   g_order[P_N];
__device__ int   g_idx[(size_t)P_N * L_N];
__device__ int   g_len[P_N];
__device__ float g_agg[(size_t)C_N * F_N];
__device__ float g_table[(size_t)C_N * 96];
__device__ int   g_blkhist[PB_BLOCKS * 8];
__device__ int   g_blkoff[PB_BLOCKS * 8];
__device__ int   g_done;

// ---------------- helpers ----------------
__device__ __forceinline__ u64 ffma2(u64 a, u64 b, u64 c) {
    u64 d;
    asm("fma.rn.f32x2 %0, %1, %2, %3;" : "=l"(d) : "l"(a), "l"(b), "l"(c));
    return d;
}
__device__ __forceinline__ float2 u2f(u64 v) {
    float2 r;
    asm("mov.b64 {%0,%1}, %2;" : "=f"(r.x), "=f"(r.y) : "l"(v));
    return r;
}
__device__ __forceinline__ u64 f2u(float a, float b) {
    u64 r;
    asm("mov.b64 %0, {%1,%2};" : "=l"(r) : "f"(a), "f"(b));
    return r;
}

__device__ __forceinline__ float tanh_ap(float x) {
    float y;
    asm("tanh.approx.f32 %0, %1;" : "=f"(y) : "f"(x));
    return y;
}
__device__ __forceinline__ float fast_sigmoid(float v) {
    return fmaf(0.5f, tanh_ap(0.5f * v), 0.5f);
}
__device__ __forceinline__ float fast_tanh(float v) { return tanh_ap(v); }

__device__ __forceinline__ void red_add_v4(float* p, float4 v) {
    asm volatile("red.global.add.v4.f32 [%0], {%1,%2,%3,%4};"
                 :: "l"(p), "f"(v.x), "f"(v.y), "f"(v.z), "f"(v.w) : "memory");
}
__device__ __forceinline__ u64 ldg64(const u64* p) {
    u64 v;
    asm("ld.global.nc.b64 %0, [%1];" : "=l"(v) : "l"(p));
    return v;
}

// stage weights as paired layout: dst[j*96 + gate*32 + 2*fy + s] = pair for k=2j+s
// pair value = (W[gate*32+2*fy][k], W[gate*32+2*fy+1][k])
__device__ __forceinline__ void stage_paired(const float* __restrict__ W, u64* dst, int tid) {
    for (int i = tid; i < 16 * 96; i += 256) {       // 1536 entries
        int j = i / 96;
        int rem = i % 96;
        int gate = rem >> 5;
        int fy2 = (rem >> 1) & 15;
        int s = rem & 1;
        int k = 2 * j + s;
        int out = gate * 32 + 2 * fy2;
        dst[i] = f2u(W[out * 32 + k], W[(out + 1) * 32 + k]);
    }
}

// ---------------- hist + per-block offsets (last-block-done) ----------------
__global__ void __launch_bounds__(256) hist_prefix_kernel(const int* __restrict__ plen) {
    __shared__ int lh[8];
    __shared__ int slast;
    int tid = threadIdx.x;
    if (tid < 8) lh[tid] = 0;
    __syncthreads();
    int i = blockIdx.x * 256 + tid;
    if (i < P_N) {
        int b = plen[i]; b = b < 0 ? 0 : (b > 7 ? 7 : b);
        atomicAdd(&lh[b], 1);
    }
    __syncthreads();
    if (tid < 8) g_blkhist[blockIdx.x * 8 + tid] = lh[tid];
    __threadfence();
    if (tid == 0) {
        int t = atomicAdd(&g_done, 1);
        slast = (t == gridDim.x - 1) ? 1 : 0;
    }
    __syncthreads();
    if (slast) {
        __threadfence();
        int local[8] = {0, 0, 0, 0, 0, 0, 0, 0};
        for (int j = tid; j < PB_BLOCKS; j += 256) {
#pragma unroll
            for (int b = 0; b < 8; b++) local[b] += g_blkhist[j * 8 + b];
        }
        if (tid < 8) lh[tid] = 0;
        __syncthreads();
#pragma unroll
        for (int b = 0; b < 8; b++) atomicAdd(&lh[b], local[b]);
        __syncthreads();
        __shared__ int base[8];
        if (tid == 0) {
            int acc = 0;
#pragma unroll
            for (int b = 7; b >= 0; b--) { int cv = lh[b]; base[b] = acc; acc += cv; }
            g_done = 0;
        }
        __syncthreads();
        if (tid < 8) {
            int b = tid;
            int acc = base[b];
            for (int j = 0; j < PB_BLOCKS; j++) {
                g_blkoff[j * 8 + b] = acc;
                acc += g_blkhist[j * 8 + b];
            }
        }
    }
}

__global__ void __launch_bounds__(256) scatter_kernel(const int* __restrict__ plen) {
    __shared__ int loff[8];
    int tid = threadIdx.x;
    if (tid < 8) loff[tid] = g_blkoff[blockIdx.x * 8 + tid];
    __syncthreads();
    int i = blockIdx.x * 256 + tid;
    if (i < P_N) {
        int b = plen[i]; b = b < 0 ? 0 : (b > 7 ? 7 : b);
        int pos = atomicAdd(&loff[b], 1);
        g_order[pos] = i;
    }
}

// ---------------- build paths ----------------
__global__ void __launch_bounds__(256, 2) build_paths_kernel(const int* __restrict__ plen,
                                                             const int* __restrict__ pci,
                                                             const float* __restrict__ praw,
                                                             const float* __restrict__ Wp,
                                                             const float* __restrict__ bp)
{
    __shared__ __align__(16) float sxx[64 * XS];
    __shared__ __align__(16) u64   sww[64 * 16];
    __shared__ int   sord[BI_TILE];
    __shared__ float sb[32];

    int tid = threadIdx.x;
    int s0 = blockIdx.x * BI_TILE;
    int rcount = min(BI_TILE, P_N - s0);

    for (int i = tid; i < 64 * 16; i += 256) {
        int d = i >> 4, o = i & 15;
        float2 w = ((const float2*)(Wp + d * 32))[o];
        sww[d * 16 + o] = f2u(w.x, w.y);
    }
    if (tid < 32) sb[tid] = bp[tid];
    if (tid < BI_TILE) {
        int row = s0 + tid;
        if (row < P_N) {
            int sr = g_order[row];
            sord[tid] = sr;
            g_len[row] = plen[sr];
            const int4* si = (const int4*)(pci + (size_t)sr * L_N);
            int4* di = (int4*)(g_idx + (size_t)row * L_N);
            di[0] = si[0]; di[1] = si[1];
        }
    }
    __syncthreads();

    for (int i = tid; i < rcount * 16; i += 256) {
        int r = i >> 4, q = i & 15;
        float4 v = ((const float4*)(praw + (size_t)sord[r] * DIN))[q];
        sxx[(4 * q + 0) * XS + r] = v.x;
        sxx[(4 * q + 1) * XS + r] = v.y;
        sxx[(4 * q + 2) * XS + r] = v.z;
        sxx[(4 * q + 3) * XS + r] = v.w;
    }
    __syncthreads();

    int px = tid >> 4, fy = tid & 15;
    int pbase = px * 8;
    u64 acc[8];
#pragma unroll
    for (int p = 0; p < 8; p++) acc[p] = 0ull;
#pragma unroll 4
    for (int k = 0; k < 64; k++) {
        u64 w = sww[k * 16 + fy];
        const float4* xr = (const float4*)(sxx + k * XS + pbase);
        float4 a = xr[0], bq = xr[1];
        float xv[8] = {a.x, a.y, a.z, a.w, bq.x, bq.y, bq.z, bq.w};
#pragma unroll
        for (int p = 0; p < 8; p++)
            acc[p] = ffma2(f2u(xv[p], xv[p]), w, acc[p]);
    }
    float b0 = sb[2 * fy], b1 = sb[2 * fy + 1];
#pragma unroll
    for (int p = 0; p < 8; p++) {
        int pp = pbase + p;
        if (pp < rcount) {
            float2 v = u2f(acc[p]);
            ((u64*)(g_p + (size_t)(s0 + pp) * F_N))[fy] =
                f2u(fmaxf(v.x + b0, 0.0f), fmaxf(v.y + b1, 0.0f));
        }
    }
}

// ---------------- build channels: init c + zero agg + step0 gi1 table ----------------
__global__ void __launch_bounds__(256, 2) build_chan_kernel(const float* __restrict__ craw,
                                                            const float* __restrict__ Wc,
                                                            const float* __restrict__ bc,
                                                            const float* __restrict__ Wi1,
                                                            const float* __restrict__ bi1,
                                                            const float* __restrict__ bh1,
                                                            float* __restrict__ c)
{
    __shared__ __align__(16) float sxx[64 * XS];
    __shared__ __align__(16) u64   sww[16 * 96];   // init W (64*16) then paired Wi1 (16*96)
    __shared__ float sb[32];
    __shared__ float sb1[96];

    int tid = threadIdx.x;
    int s0 = blockIdx.x * BI_TILE;
    int rcount = min(BI_TILE, C_N - s0);

    for (int i = tid; i < 64 * 16; i += 256) {
        int d = i >> 4, o = i & 15;
        float2 w = ((const float2*)(Wc + d * 32))[o];
        sww[d * 16 + o] = f2u(w.x, w.y);
    }
    if (tid < 32) sb[tid] = bc[tid];
    if (tid < 96) sb1[tid] = bi1[tid] + (tid < 64 ? bh1[tid] : 0.0f);
    __syncthreads();

    for (int i = tid; i < rcount * 16; i += 256) {
        int r = i >> 4, q = i & 15;
        float4 v = ((const float4*)(craw + (size_t)(s0 + r) * DIN))[q];
        sxx[(4 * q + 0) * XS + r] = v.x;
        sxx[(4 * q + 1) * XS + r] = v.y;
        sxx[(4 * q + 2) * XS + r] = v.z;
        sxx[(4 * q + 3) * XS + r] = v.w;
    }
    __syncthreads();

    int px = tid >> 4, fy = tid & 15;
    int pbase = px * 8;
    u64 acc[8];
#pragma unroll
    for (int p = 0; p < 8; p++) acc[p] = 0ull;
#pragma unroll 4
    for (int k = 0; k < 64; k++) {
        u64 w = sww[k * 16 + fy];
        const float4* xr = (const float4*)(sxx + k * XS + pbase);
        float4 a = xr[0], bq = xr[1];
        float xv[8] = {a.x, a.y, a.z, a.w, bq.x, bq.y, bq.z, bq.w};
#pragma unroll
        for (int p = 0; p < 8; p++)
            acc[p] = ffma2(f2u(xv[p], xv[p]), w, acc[p]);
    }
    float cres[8][2];
    float b0 = sb[2 * fy], b1 = sb[2 * fy + 1];
#pragma unroll
    for (int p = 0; p < 8; p++) {
        int pp = pbase + p;
        float2 v = u2f(acc[p]);
        float r0 = fmaxf(v.x + b0, 0.0f);
        float r1 = fmaxf(v.y + b1, 0.0f);
        cres[p][0] = r0; cres[p][1] = r1;
        if (pp < rcount)
            ((u64*)(c + (size_t)(s0 + pp) * F_N))[fy] = f2u(r0, r1);
    }

    __syncthreads();
    for (int i = tid; i < rcount * 8; i += 256)
        ((float4*)(g_agg + (size_t)s0 * F_N))[i] = make_float4(0.f, 0.f, 0.f, 0.f);
#pragma unroll
    for (int p = 0; p < 8; p++) {
        int pp = pbase + p;
        if (pp < rcount) {
            sxx[(2 * fy) * XS + pp]     = cres[p][0];
            sxx[(2 * fy + 1) * XS + pp] = cres[p][1];
        }
    }
    stage_paired(Wi1, sww, tid);
    __syncthreads();

    u64 tr[8], tz[8], tn[8];
#pragma unroll
    for (int p = 0; p < 8; p++) { tr[p] = 0ull; tz[p] = 0ull; tn[p] = 0ull; }
#pragma unroll 4
    for (int j = 0; j < 16; j++) {
        const u64* wj = sww + j * 96;
        ulonglong2 wr = *(const ulonglong2*)(wj + 2 * fy);
        ulonglong2 wz = *(const ulonglong2*)(wj + 32 + 2 * fy);
        ulonglong2 wn = *(const ulonglong2*)(wj + 64 + 2 * fy);
        const float4* x0 = (const float4*)(sxx + (2 * j) * XS + pbase);
        const float4* x1 = (const float4*)(sxx + (2 * j + 1) * XS + pbase);
        float4 a0 = x0[0], b0q = x0[1], a1 = x1[0], b1q = x1[1];
        float xe[8] = {a0.x, a0.y, a0.z, a0.w, b0q.x, b0q.y, b0q.z, b0q.w};
        float xo[8] = {a1.x, a1.y, a1.z, a1.w, b1q.x, b1q.y, b1q.z, b1q.w};
#pragma unroll
        for (int p = 0; p < 8; p++) {
            u64 de = f2u(xe[p], xe[p]);
            tr[p] = ffma2(de, wr.x, tr[p]);
            tz[p] = ffma2(de, wz.x, tz[p]);
            tn[p] = ffma2(de, wn.x, tn[p]);
            u64 dq = f2u(xo[p], xo[p]);
            tr[p] = ffma2(dq, wr.y, tr[p]);
            tz[p] = ffma2(dq, wz.y, tz[p]);
            tn[p] = ffma2(dq, wn.y, tn[p]);
        }
    }
    float br0 = sb1[2 * fy],      br1 = sb1[2 * fy + 1];
    float bz0 = sb1[32 + 2 * fy], bz1 = sb1[32 + 2 * fy + 1];
    float bn0 = sb1[64 + 2 * fy], bn1 = sb1[64 + 2 * fy + 1];
#pragma unroll
    for (int p = 0; p < 8; p++) {
        int pp = pbase + p;
        if (pp < rcount) {
            u64* trow = (u64*)(g_table + (size_t)(s0 + pp) * 96);
            float2 a0 = u2f(tr[p]), a1 = u2f(tz[p]), a2 = u2f(tn[p]);
            trow[fy]      = f2u(a0.x + br0, a0.y + br1);
            trow[16 + fy] = f2u(a1.x + bz0, a1.y + bz1);
            trow[32 + fy] = f2u(a2.x + bn0, a2.y + bn1);
        }
    }
}

// ---------------- scan11: paired-weight layout (3 LDS.128/j), warp-autonomous ----------------
__global__ void __launch_bounds__(256, 2) scan11_kernel(const float* __restrict__ Wh,
                                                        const float* __restrict__ bh,
                                                        float* __restrict__ final_out)
{
    __shared__ __align__(16) u64   sww[16 * 96];     // paired layout
    __shared__ __align__(16) float shf[16 * SROW];
    __shared__ unsigned short sidx[STILE * L_N];
    __shared__ short slen[STILE];
    __shared__ float sbhn[32];

    int tid = threadIdx.x;
    int s0 = blockIdx.x * STILE;
    int pcount = min(STILE, P_N - s0);

    stage_paired(Wh, sww, tid);
    if (tid < 32) sbhn[tid] = bh[64 + tid];
    if (tid < STILE) slen[tid] = (tid < pcount) ? (short)g_len[s0 + tid] : (short)-1;
    for (int i = tid; i < STILE * L_N; i += 256)
        sidx[i] = (i < pcount * L_N) ? (unsigned short)g_idx[(size_t)s0 * L_N + i] : (unsigned short)0;
    if (pcount < STILE) {
        for (int i = tid; i < 16 * SROW; i += 256) shf[i] = 0.0f;
        __syncthreads();
    }
    for (int i = tid; i < pcount * 8; i += 256) {
        int p = i >> 3, kq = i & 7;
        float4 v = ((const float4*)(g_p + (size_t)s0 * F_N))[i];
        float* r0 = &shf[(2 * kq) * SROW + 2 * p];
        r0[0] = v.x; r0[1] = v.y;
        float* r1 = &shf[(2 * kq + 1) * SROW + 2 * p];
        r1[0] = v.z; r1[1] = v.w;
    }
    __syncthreads();

    int px = tid >> 4;
    int fy = tid & 15;
    int pbase = px * 8;
    int wfirst = (tid >> 5) * 16;
    int tmax = slen[wfirst];

    for (int t = 0; t <= tmax; t++) {
        u64 ar[8], az[8], an[8];
#pragma unroll
        for (int p = 0; p < 8; p++) { ar[p] = 0ull; az[p] = 0ull; an[p] = 0ull; }

#pragma unroll 4
        for (int j = 0; j < 16; j++) {
            const u64* wj = sww + j * 96;
            ulonglong2 wr = *(const ulonglong2*)(wj + 2 * fy);
            ulonglong2 wz = *(const ulonglong2*)(wj + 32 + 2 * fy);
            ulonglong2 wn = *(const ulonglong2*)(wj + 64 + 2 * fy);
            const float4* hq = (const float4*)(shf + j * SROW + 2 * pbase);
            float4 q0 = hq[0], q1 = hq[1], q2 = hq[2], q3 = hq[3];
            float qe[8] = {q0.x, q0.z, q1.x, q1.z, q2.x, q2.z, q3.x, q3.z};
            float qo[8] = {q0.y, q0.w, q1.y, q1.w, q2.y, q2.w, q3.y, q3.w};
#pragma unroll
            for (int p = 0; p < 8; p++) {
                u64 he = f2u(qe[p], qe[p]);
                ar[p] = ffma2(he, wr.x, ar[p]);
                az[p] = ffma2(he, wz.x, az[p]);
                an[p] = ffma2(he, wn.x, an[p]);
                u64 ho = f2u(qo[p], qo[p]);
                ar[p] = ffma2(ho, wr.y, ar[p]);
                az[p] = ffma2(ho, wz.y, az[p]);
                an[p] = ffma2(ho, wn.y, an[p]);
            }
        }
        __syncwarp();

        {
            u64 ga0, ga1, ga2, gb0, gb1, gb2;
            {
                int cha = sidx[(pbase + 0) * L_N + t];
                const u64* tga = (const u64*)(g_table + (size_t)cha * 96);
                ga0 = ldg64(tga + fy); ga1 = ldg64(tga + 16 + fy); ga2 = ldg64(tga + 32 + fy);
                int chb = sidx[(pbase + 1) * L_N + t];
                const u64* tgb = (const u64*)(g_table + (size_t)chb * 96);
                gb0 = ldg64(tgb + fy); gb1 = ldg64(tgb + 16 + fy); gb2 = ldg64(tgb + 32 + fy);
            }
#pragma unroll
            for (int pr = 0; pr < 4; pr++) {
                u64 na0 = 0, na1 = 0, na2 = 0, nb0 = 0, nb1 = 0, nb2 = 0;
                if (pr < 3) {
                    int cha = sidx[(pbase + 2 * pr + 2) * L_N + t];
                    const u64* tga = (const u64*)(g_table + (size_t)cha * 96);
                    na0 = ldg64(tga + fy); na1 = ldg64(tga + 16 + fy); na2 = ldg64(tga + 32 + fy);
                    int chb = sidx[(pbase + 2 * pr + 3) * L_N + t];
                    const u64* tgb = (const u64*)(g_table + (size_t)chb * 96);
                    nb0 = ldg64(tgb + fy); nb1 = ldg64(tgb + 16 + fy); nb2 = ldg64(tgb + 32 + fy);
                }
#pragma unroll
                for (int s = 0; s < 2; s++) {
                    int pp = pbase + 2 * pr + s;
                    u64 cg0 = s ? gb0 : ga0;
                    u64 cg1 = s ? gb1 : ga1;
                    u64 cg2 = s ? gb2 : ga2;
                    int p = 2 * pr + s;
                    bool active = (t <= slen[pp]);
                    float2 gr = u2f(cg0), gz = u2f(cg1), gn = u2f(cg2);
                    float2 vr = u2f(ar[p]), vz = u2f(az[p]), vn = u2f(an[p]);
                    float2 hold = *(const float2*)(shf + fy * SROW + 2 * pp);
                    float h0, h1;
                    {
                        float r = fast_sigmoid(gr.x + vr.x);
                        float z = fast_sigmoid(gz.x + vz.x);
                        float n = fast_tanh(gn.x + r * (vn.x + sbhn[2 * fy]));
                        h0 = n + z * (hold.x - n);
                    }
                    {
                        float r = fast_sigmoid(gr.y + vr.y);
                        float z = fast_sigmoid(gz.y + vz.y);
                        float n = fast_tanh(gn.y + r * (vn.y + sbhn[2 * fy + 1]));
                        h1 = n + z * (hold.y - n);
                    }
                    if (active)
                        *(float2*)(shf + fy * SROW + 2 * pp) = make_float2(h0, h1);
                }
                ga0 = na0; ga1 = na1; ga2 = na2;
                gb0 = nb0; gb1 = nb1; gb2 = nb2;
            }
        }
        __syncwarp();
    }

    __syncthreads();

    int p = tid & (STILE - 1);
    int kc = tid >> 7;
    if (p < pcount) {
        float v[16];
#pragma unroll
        for (int j = 0; j < 16; j++) {
            int f = kc * 16 + j;
            v[j] = shf[(f >> 1) * SROW + 2 * p + (f & 1)];
        }
        float4* dst;
        if (final_out) {
            int ord = g_order[s0 + p];
            dst = (float4*)(final_out + (size_t)ord * F_N + kc * 16);
        } else {
            dst = (float4*)(g_p + (size_t)(s0 + p) * F_N + kc * 16);
        }
#pragma unroll
        for (int q = 0; q < 4; q++)
            dst[q] = make_float4(v[4 * q], v[4 * q + 1], v[4 * q + 2], v[4 * q + 3]);
        int ln = slen[p];
#pragma unroll 1
        for (int t = 0; t <= ln; t++) {
            int ch = sidx[p * L_N + t];
            float* base = g_agg + (size_t)ch * F_N + kc * 16;
            red_add_v4(base + 0,  make_float4(v[0],  v[1],  v[2],  v[3]));
            red_add_v4(base + 4,  make_float4(v[4],  v[5],  v[6],  v[7]));
            red_add_v4(base + 8,  make_float4(v[8],  v[9],  v[10], v[11]));
            red_add_v4(base + 12, make_float4(v[12], v[13], v[14], v[15]));
        }
    }
}

// ---------------- layer2h: paired weights, 128 rows/block, fused gi2+gh2, gi1 table ----------------
__global__ void __launch_bounds__(256, 2) layer2h_kernel(float* __restrict__ c,
                                                         const float* __restrict__ Wi2,
                                                         const float* __restrict__ Wh2,
                                                         const float* __restrict__ bi2,
                                                         const float* __restrict__ bh2,
                                                         const float* __restrict__ Wi1,
                                                         const float* __restrict__ bi1,
                                                         const float* __restrict__ bh1,
                                                         int want_table)
{
    __shared__ __align__(16) u64   swa[16 * 96];     // paired Wi2 -> paired Wi1
    __shared__ __align__(16) u64   swh[16 * 96];     // paired Wh2
    __shared__ __align__(16) float sagg[32 * XS];
    __shared__ __align__(16) float sc[32 * XS];
    __shared__ float sbi[96];
    __shared__ float sbhn2[32];
    __shared__ float sb1[96];

    int tid = threadIdx.x;
    int s0 = blockIdx.x * L2T;
    int rcount = min(L2T, C_N - s0);

    stage_paired(Wi2, swa, tid);
    stage_paired(Wh2, swh, tid);
    if (tid < 96) {
        sbi[tid] = bi2[tid] + (tid < 64 ? bh2[tid] : 0.0f);
        sb1[tid] = bi1[tid] + (tid < 64 ? bh1[tid] : 0.0f);
    }
    if (tid < 32) sbhn2[tid] = bh2[64 + tid];
    if (rcount < L2T) {
        for (int i = tid; i < 32 * L2T; i += 256) {
            int p = i & (L2T - 1);
            if (p >= rcount) { sagg[(i >> 7) * XS + p] = 0.0f; sc[(i >> 7) * XS + p] = 0.0f; }
        }
    }
    for (int i = tid; i < rcount * 8; i += 256) {
        int p = i >> 3, kq = i & 7;
        float4 va = ((const float4*)(g_agg + (size_t)s0 * F_N))[i];
        sagg[(4 * kq + 0) * XS + p] = va.x;
        sagg[(4 * kq + 1) * XS + p] = va.y;
        sagg[(4 * kq + 2) * XS + p] = va.z;
        sagg[(4 * kq + 3) * XS + p] = va.w;
        ((float4*)(g_agg + (size_t)s0 * F_N))[i] = make_float4(0.f, 0.f, 0.f, 0.f);
        float4 vc = ((const float4*)(c + (size_t)s0 * F_N))[i];
        sc[(4 * kq + 0) * XS + p] = vc.x;
        sc[(4 * kq + 1) * XS + p] = vc.y;
        sc[(4 * kq + 2) * XS + p] = vc.z;
        sc[(4 * kq + 3) * XS + p] = vc.w;
    }
    __syncthreads();

    int px = tid >> 4, fy = tid & 15;
    int pbase = px * 8;

    u64 ir[8], iz[8], in_[8];
#pragma unroll
    for (int p = 0; p < 8; p++) { ir[p] = 0ull; iz[p] = 0ull; in_[p] = 0ull; }
#pragma unroll 4
    for (int j = 0; j < 16; j++) {
        const u64* wj = swa + j * 96;
        ulonglong2 wr = *(const ulonglong2*)(wj + 2 * fy);
        ulonglong2 wz = *(const ulonglong2*)(wj + 32 + 2 * fy);
        ulonglong2 wn = *(const ulonglong2*)(wj + 64 + 2 * fy);
        const float4* x0 = (const float4*)(sagg + (2 * j) * XS + pbase);
        const float4* x1 = (const float4*)(sagg + (2 * j + 1) * XS + pbase);
        float4 a0 = x0[0], b0q = x0[1], a1 = x1[0], b1q = x1[1];
        float xe[8] = {a0.x, a0.y, a0.z, a0.w, b0q.x, b0q.y, b0q.z, b0q.w};
        float xo[8] = {a1.x, a1.y, a1.z, a1.w, b1q.x, b1q.y, b1q.z, b1q.w};
#pragma unroll
        for (int p = 0; p < 8; p++) {
            u64 de = f2u(xe[p], xe[p]);
            ir[p]  = ffma2(de, wr.x, ir[p]);
            iz[p]  = ffma2(de, wz.x, iz[p]);
            in_[p] = ffma2(de, wn.x, in_[p]);
            u64 dq = f2u(xo[p], xo[p]);
            ir[p]  = ffma2(dq, wr.y, ir[p]);
            iz[p]  = ffma2(dq, wz.y, iz[p]);
            in_[p] = ffma2(dq, wn.y, in_[p]);
        }
    }

    u64 hr_[8], hz_[8], hn_[8];
#pragma unroll
    for (int p = 0; p < 8; p++) { hr_[p] = 0ull; hz_[p] = 0ull; hn_[p] = 0ull; }
#pragma unroll 4
    for (int j = 0; j < 16; j++) {
        const u64* wj = swh + j * 96;
        ulonglong2 wr = *(const ulonglong2*)(wj + 2 * fy);
        ulonglong2 wz = *(const ulonglong2*)(wj + 32 + 2 * fy);
        ulonglong2 wn = *(const ulonglong2*)(wj + 64 + 2 * fy);
        const float4* x0 = (const float4*)(sc + (2 * j) * XS + pbase);
        const float4* x1 = (const float4*)(sc + (2 * j + 1) * XS + pbase);
        float4 a0 = x0[0], b0q = x0[1], a1 = x1[0], b1q = x1[1];
        float xe[8] = {a0.x, a0.y, a0.z, a0.w, b0q.x, b0q.y, b0q.z, b0q.w};
        float xo[8] = {a1.x, a1.y, a1.z, a1.w, b1q.x, b1q.y, b1q.z, b1q.w};
#pragma unroll
        for (int p = 0; p < 8; p++) {
            u64 de = f2u(xe[p], xe[p]);
            hr_[p] = ffma2(de, wr.x, hr_[p]);
            hz_[p] = ffma2(de, wz.x, hz_[p]);
            hn_[p] = ffma2(de, wn.x, hn_[p]);
            u64 dq = f2u(xo[p], xo[p]);
            hr_[p] = ffma2(dq, wr.y, hr_[p]);
            hz_[p] = ffma2(dq, wz.y, hz_[p]);
            hn_[p] = ffma2(dq, wn.y, hn_[p]);
        }
    }

    float hn2[8][2];
#pragma unroll
    for (int p = 0; p < 8; p++) {
        int pp = pbase + p;
        if (pp < rcount) {
            int ch = s0 + pp;
            u64* cdst = (u64*)(c + (size_t)ch * F_N);
            float2 vi_r = u2f(ir[p]),  vi_z = u2f(iz[p]),  vi_n = u2f(in_[p]);
            float2 vh_r = u2f(hr_[p]), vh_z = u2f(hz_[p]), vh_n = u2f(hn_[p]);
#pragma unroll
            for (int half = 0; half < 2; half++) {
                int f = 2 * fy + half;
                float a_ir = half ? vi_r.y : vi_r.x;
                float a_iz = half ? vi_z.y : vi_z.x;
                float a_in = half ? vi_n.y : vi_n.x;
                float a_hr = half ? vh_r.y : vh_r.x;
                float a_hz = half ? vh_z.y : vh_z.x;
                float a_hn = half ? vh_n.y : vh_n.x;
                float r = fast_sigmoid(a_ir + sbi[f] + a_hr);
                float z = fast_sigmoid(a_iz + sbi[32 + f] + a_hz);
                float n = fast_tanh(a_in + sbi[64 + f] + r * (a_hn + sbhn2[f]));
                float hold = sc[f * XS + pp];
                hn2[p][half] = n + z * (hold - n);
            }
            cdst[fy] = f2u(hn2[p][0], hn2[p][1]);
        }
    }

    if (!want_table) return;
    __syncthreads();

#pragma unroll
    for (int p = 0; p < 8; p++) {
        int pp = pbase + p;
        if (pp < rcount) {
            sagg[(2 * fy) * XS + pp]     = hn2[p][0];
            sagg[(2 * fy + 1) * XS + pp] = hn2[p][1];
        }
    }
    stage_paired(Wi1, swa, tid);
    __syncthreads();

    u64 tr[8], tz[8], tn[8];
#pragma unroll
    for (int p = 0; p < 8; p++) { tr[p] = 0ull; tz[p] = 0ull; tn[p] = 0ull; }
#pragma unroll 4
    for (int j = 0; j < 16; j++) {
        const u64* wj = swa + j * 96;
        ulonglong2 wr = *(const ulonglong2*)(wj + 2 * fy);
        ulonglong2 wz = *(const ulonglong2*)(wj + 32 + 2 * fy);
        ulonglong2 wn = *(const ulonglong2*)(wj + 64 + 2 * fy);
        const float4* x0 = (const float4*)(sagg + (2 * j) * XS + pbase);
        const float4* x1 = (const float4*)(sagg + (2 * j + 1) * XS + pbase);
        float4 a0 = x0[0], b0q = x0[1], a1 = x1[0], b1q = x1[1];
        float xe[8] = {a0.x, a0.y, a0.z, a0.w, b0q.x, b0q.y, b0q.z, b0q.w};
        float xo[8] = {a1.x, a1.y, a1.z, a1.w, b1q.x, b1q.y, b1q.z, b1q.w};
#pragma unroll
        for (int p = 0; p < 8; p++) {
            u64 de = f2u(xe[p], xe[p]);
            tr[p] = ffma2(de, wr.x, tr[p]);
            tz[p] = ffma2(de, wz.x, tz[p]);
            tn[p] = ffma2(de, wn.x, tn[p]);
            u64 dq = f2u(xo[p], xo[p]);
            tr[p] = ffma2(dq, wr.y, tr[p]);
            tz[p] = ffma2(dq, wz.y, tz[p]);
            tn[p] = ffma2(dq, wn.y, tn[p]);
        }
    }
    float br0 = sb1[2 * fy],      br1 = sb1[2 * fy + 1];
    float bz0 = sb1[32 + 2 * fy], bz1 = sb1[32 + 2 * fy + 1];
    float bn0 = sb1[64 + 2 * fy], bn1 = sb1[64 + 2 * fy + 1];
#pragma unroll
    for (int p = 0; p < 8; p++) {
        int pp = pbase + p;
        if (pp < rcount) {
            u64* trow = (u64*)(g_table + (size_t)(s0 + pp) * 96);
            float2 a0 = u2f(tr[p]), a1 = u2f(tz[p]), a2 = u2f(tn[p]);
            trow[fy]      = f2u(a0.x + br0, a0.y + br1);
            trow[16 + fy] = f2u(a1.x + bz0, a1.y + bz1);
            trow[32 + fy] = f2u(a2.x + bn0, a2.y + bn1);
        }
    }
}

// ---------------- launch ----------------
extern "C" void kernel_launch(void* const* d_in, const int* in_sizes, int n_in,
                              void* d_out, int out_size)
{
    const float* path_raw    = (const float*)d_in[0];
    const float* channel_raw = (const float*)d_in[1];
    const int*   pci         = (const int*)d_in[2];
    const int*   plen        = (const int*)d_in[3];
    // d_in[4] = num_steps (constant 5)
    const float* Wp  = (const float*)d_in[5];
    const float* bp  = (const float*)d_in[6];
    const float* Wc  = (const float*)d_in[7];
    const float* bc  = (const float*)d_in[8];
    const float* Wi1 = (const float*)d_in[9];
    const float* Wh1 = (const float*)d_in[10];
    const float* bi1 = (const float*)d_in[11];
    const float* bh1 = (const float*)d_in[12];
    const float* Wi2 = (const float*)d_in[13];
    const float* Wh2 = (const float*)d_in[14];
    const float* bi2 = (const float*)d_in[15];
    const float* bh2 = (const float*)d_in[16];

    float* outp = (float*)d_out;
    float* c    = outp + (size_t)P_N * F_N;

    int gridScan = (P_N + STILE - 1) / STILE;

    hist_prefix_kernel<<<PB_BLOCKS, 256>>>(plen);
    scatter_kernel<<<PB_BLOCKS, 256>>>(plen);
    build_paths_kernel<<<PB2, 256>>>(plen, pci, path_raw, Wp, bp);
    build_chan_kernel<<<CB2, 256>>>(channel_raw, Wc, bc, Wi1, bi1, bh1, c);
    for (int st = 0; st < NSTEPS; st++) {
        scan11_kernel<<<gridScan, 256>>>(Wh1, bh1, (st == NSTEPS - 1) ? outp : nullptr);
        layer2h_kernel<<<L2B, 256>>>(c, Wi2, Wh2, bi2, bh2, Wi1, bi1, bh1,
                                     (st < NSTEPS - 1) ? 1 : 0);
    }
}